// round 8
// baseline (speedup 1.0000x reference)
#include <cuda_runtime.h>
#include <math.h>
#include <stdint.h>

#define BB 4
#define CC 192
#define NN 4096
#define NHEADS 8
#define HD 24
#define PLENC 256

// ---------------- device scratch ----------------
__device__ __align__(256) float g_xc[BB * NN * CC];
__device__ __align__(256) float g_t[BB * NN * CC];
__device__ __align__(256) float g_qkvs[BB * NN * 768];
__device__ __align__(256) float g_qn[BB * NHEADS * NN * HD];
__device__ __align__(256) float g_qs[BB * NHEADS * NN * HD];
__device__ __align__(256) float g_kvmap[BB * 16 * NN * HD];
__device__ __align__(256) float g_pooled[BB * PLENC * CC];
__device__ __align__(256) float g_kvp[BB * PLENC * 384];
__device__ __align__(256) float g_kpn[BB * NHEADS * PLENC * HD];
__device__ __align__(256) float g_vpn[BB * NHEADS * PLENC * HD];
__device__ __align__(256) float g_ao[BB * NN * CC];
__device__ __align__(256) float g_tmp[BB * NN * CC];
__device__ __align__(256) float g_Wcat[768 * 192];
__device__ __align__(256) float g_bcat[768];
__device__ __align__(256) float g_cpb[32768 * NHEADS];
__device__ __align__(256) float g_Wc2[1728 * 192];
__device__ __align__(256) float g_lt2[NHEADS * 216];
__device__ __align__(256) float g_w2[BB * NHEADS * NN * 12];

// ---------------- tf32 helpers ----------------
__device__ __forceinline__ unsigned f2tf(float f) {
    unsigned u;
    asm("cvt.rna.tf32.f32 %0, %1;" : "=r"(u) : "f"(f));
    return u;
}
__device__ __forceinline__ void split_tf(float f, unsigned& hi, unsigned& lo) {
    hi = f2tf(f);
    lo = f2tf(f - __uint_as_float(hi));
}
__device__ __forceinline__ void split_tf_f(float f, float& hi, float& lo) {
    unsigned h, l;
    split_tf(f, h, l);
    hi = __uint_as_float(h);
    lo = __uint_as_float(l);
}
__device__ __forceinline__ void mma8(float* d, const unsigned* a, const unsigned* b) {
    asm volatile(
        "mma.sync.aligned.m16n8k8.row.col.f32.tf32.tf32.f32 "
        "{%0,%1,%2,%3}, {%4,%5,%6,%7}, {%8,%9}, {%0,%1,%2,%3};"
        : "+f"(d[0]), "+f"(d[1]), "+f"(d[2]), "+f"(d[3])
        : "r"(a[0]), "r"(a[1]), "r"(a[2]), "r"(a[3]), "r"(b[0]), "r"(b[1]));
}

// ---------------- prep kernels ----------------
__global__ void k_prep_w(const float* __restrict__ qw, const float* __restrict__ qb,
                         const float* __restrict__ kvw, const float* __restrict__ kvb,
                         const float* __restrict__ srw, const float* __restrict__ srb,
                         const float* __restrict__ lt) {
    int idx = blockIdx.x * 256 + threadIdx.x;
    if (idx < 768 * 192) {
        int o = idx / 192, c = idx - o * 192;
        float v;
        if (o < 192)      v = qw[o * 192 + c];
        else if (o < 576) v = kvw[(o - 192) * 192 + c];
        else              v = srw[(o - 576) * 192 + c];
        g_Wcat[idx] = v;
    }
    if (idx < 768) {
        float v;
        if (idx < 192)      v = qb[idx];
        else if (idx < 576) v = kvb[idx - 192];
        else                v = srb[idx - 576];
        g_bcat[idx] = v;
    }
    if (idx < 1728) {
        int h = idx / 216;
        int r = idx - h * 216;
        int l = r / 24, d = r - l * 24;
        g_lt2[idx] = lt[h * 216 + d * 9 + l];
    }
}

__global__ void k_prep_wc(const float* __restrict__ w) {
    int idx = blockIdx.x * 256 + threadIdx.x;
    if (idx >= 331776) return;
    int o = idx / 1728;
    int r = idx - o * 1728;
    int c = r / 9, t = r - c * 9;
    g_Wc2[(c * 9 + t) * 192 + o] = w[idx];
}

__global__ void __launch_bounds__(256) k_prep_cpb(const float* __restrict__ tab,
                           const float* __restrict__ c1w, const float* __restrict__ c1b,
                           const float* __restrict__ c2w, const float* __restrict__ c2b,
                           int T) {
    __shared__ float s1w[1024], s1b[512], s2[512 * 8];
    int tid = threadIdx.x;
#pragma unroll
    for (int i = 0; i < 4; i++) s1w[tid + i * 256] = c1w[tid + i * 256];
#pragma unroll
    for (int i = 0; i < 2; i++) s1b[tid + i * 256] = c1b[tid + i * 256];
#pragma unroll
    for (int i = 0; i < 16; i++) {
        int idx = tid + i * 256;
        int j = idx >> 3, h = idx & 7;
        s2[idx] = c2w[h * 512 + j];
    }
    __syncthreads();
    int t = blockIdx.x * 256 + tid;
    if (t >= T || t >= 32768) return;
    float t0 = tab[2 * t], t1 = tab[2 * t + 1];
    float acc[8];
#pragma unroll
    for (int h = 0; h < 8; h++) acc[h] = 0.f;
    for (int j = 0; j < 512; j++) {
        float hv = fmaxf(t0 * s1w[2 * j] + t1 * s1w[2 * j + 1] + s1b[j], 0.f);
#pragma unroll
        for (int h = 0; h < 8; h++) acc[h] += hv * s2[j * 8 + h];
    }
#pragma unroll
    for (int h = 0; h < 8; h++) g_cpb[t * 8 + h] = acc[h] + c2b[h];
}

// ---------------- conv 3x3 as implicit GEMM (3xTF32 mma, pre-split smem) ----------------
__global__ void __launch_bounds__(256) k_conv_tc(const float* __restrict__ x,
                                                 const float* __restrict__ bias) {
    extern __shared__ float sm[];
    float* s_xh = sm;
    float* s_xl = s_xh + 2240;
    float* s_wh = s_xl + 2240;
    float* s_wl = s_wh + 5184;

    int b = blockIdx.x >> 5;
    int y0 = (blockIdx.x & 31) * 2;
    int ocg = blockIdx.y;
    int tid = threadIdx.x;
    int wid = tid >> 5, lane = tid & 31;
    int g = lane >> 2, tcol = lane & 3;
    int wm0 = (wid >> 1) * 32, wn0 = (wid & 1) * 32;

    float acc[2][4][4];
#pragma unroll
    for (int a = 0; a < 2; a++)
#pragma unroll
        for (int bq = 0; bq < 4; bq++)
#pragma unroll
            for (int c = 0; c < 4; c++) acc[a][bq][c] = 0.f;

    const float* xb = x + (size_t)b * 192 * 4096;

    for (int c0 = 0; c0 < 192; c0 += 8) {
#pragma unroll
        for (int i = 0; i < 2; i++) {
            int f = tid + i * 256;
            int c = f >> 6;
            int rem = f & 63;
            int r = rem >> 4, seg = rem & 15;
            int gy = y0 - 1 + r;
            float4 v = make_float4(0.f, 0.f, 0.f, 0.f);
            if (gy >= 0 && gy < 64)
                v = *(const float4*)(xb + ((size_t)(c0 + c) * 64 + gy) * 64 + seg * 4);
            float4 hv, lv;
            split_tf_f(v.x, hv.x, lv.x); split_tf_f(v.y, hv.y, lv.y);
            split_tf_f(v.z, hv.z, lv.z); split_tf_f(v.w, hv.w, lv.w);
            int off = c * 280 + r * 68 + 1 + seg * 4;
            s_xh[off + 0] = hv.x; s_xh[off + 1] = hv.y; s_xh[off + 2] = hv.z; s_xh[off + 3] = hv.w;
            s_xl[off + 0] = lv.x; s_xl[off + 1] = lv.y; s_xl[off + 2] = lv.z; s_xl[off + 3] = lv.w;
        }
        if (tid < 64) {
            int c = tid >> 3;
            int rr = tid & 7;
            int r = rr >> 1, side = rr & 1;
            int off = c * 280 + r * 68 + (side ? 65 : 0);
            s_xh[off] = 0.f; s_xl[off] = 0.f;
        }
#pragma unroll
        for (int i = 0; i < 5; i++) {
            int f = tid + i * 256;
            if (f < 1152) {
                int krow = f >> 4, seg = f & 15;
                float4 wv = *(const float4*)(g_Wc2 + ((size_t)(c0 * 9) + krow) * 192 + ocg * 64 + seg * 4);
                float4 hv, lv;
                split_tf_f(wv.x, hv.x, lv.x); split_tf_f(wv.y, hv.y, lv.y);
                split_tf_f(wv.z, hv.z, lv.z); split_tf_f(wv.w, hv.w, lv.w);
                int off = krow * 72 + seg * 4;
                *(float4*)(s_wh + off) = hv;
                *(float4*)(s_wl + off) = lv;
            }
        }
        __syncthreads();

#pragma unroll
        for (int t = 0; t < 9; t++) {
            int dh = t / 3, dw = t - dh * 3;
            unsigned bh[4][2], bl[4][2];
#pragma unroll
            for (int nt = 0; nt < 4; nt++) {
                int o = wn0 + nt * 8 + g;
                int kr0 = (tcol * 9 + t) * 72 + o;
                int kr1 = ((tcol + 4) * 9 + t) * 72 + o;
                bh[nt][0] = __float_as_uint(s_wh[kr0]);
                bl[nt][0] = __float_as_uint(s_wl[kr0]);
                bh[nt][1] = __float_as_uint(s_wh[kr1]);
                bl[nt][1] = __float_as_uint(s_wl[kr1]);
            }
#pragma unroll
            for (int mt = 0; mt < 2; mt++) {
                int mbase = wm0 + mt * 16;
                int rA = (mbase >> 6) + dh;
                int col0 = (mbase & 63) + g + dw;
                int base0 = tcol * 280 + rA * 68 + col0;
                int base1 = (tcol + 4) * 280 + rA * 68 + col0;
                unsigned ah[4], al[4];
                ah[0] = __float_as_uint(s_xh[base0]);
                ah[1] = __float_as_uint(s_xh[base0 + 8]);
                ah[2] = __float_as_uint(s_xh[base1]);
                ah[3] = __float_as_uint(s_xh[base1 + 8]);
                al[0] = __float_as_uint(s_xl[base0]);
                al[1] = __float_as_uint(s_xl[base0 + 8]);
                al[2] = __float_as_uint(s_xl[base1]);
                al[3] = __float_as_uint(s_xl[base1 + 8]);
                // interleaved: independent accumulators between dependent mmas
#pragma unroll
                for (int nt = 0; nt < 4; nt++) mma8(acc[mt][nt], al, bh[nt]);
#pragma unroll
                for (int nt = 0; nt < 4; nt++) mma8(acc[mt][nt], ah, bl[nt]);
#pragma unroll
                for (int nt = 0; nt < 4; nt++) mma8(acc[mt][nt], ah, bh[nt]);
            }
        }
        __syncthreads();
    }
    const float* bb = bias + ocg * 64;
    size_t rowbase = (size_t)b * 4096 + (size_t)y0 * 64;
#pragma unroll
    for (int mt = 0; mt < 2; mt++) {
#pragma unroll
        for (int nt = 0; nt < 4; nt++) {
            int r0 = wm0 + mt * 16 + g;
            int cc = wn0 + nt * 8 + 2 * tcol;
            float b0v = bb[cc], b1v = bb[cc + 1];
            float* o0 = g_xc + (rowbase + r0) * 192 + ocg * 64 + cc;
            o0[0] = acc[mt][nt][0] + b0v;
            o0[1] = acc[mt][nt][1] + b1v;
            float* o1 = g_xc + (rowbase + r0 + 8) * 192 + ocg * 64 + cc;
            o1[0] = acc[mt][nt][2] + b0v;
            o1[1] = acc[mt][nt][3] + b1v;
        }
    }
}

// ---------------- row LN ----------------
__global__ void k_ln_rows(const float* __restrict__ gam, const float* __restrict__ bet) {
    int row = blockIdx.x * 8 + (threadIdx.x >> 5);
    int lane = threadIdx.x & 31;
    const float* src = g_xc + (size_t)row * 192;
    float v[6];
    float s = 0.f, q = 0.f;
#pragma unroll
    for (int j = 0; j < 6; j++) {
        v[j] = src[lane + j * 32];
        s += v[j]; q += v[j] * v[j];
    }
#pragma unroll
    for (int off = 16; off; off >>= 1) {
        s += __shfl_xor_sync(0xffffffffu, s, off);
        q += __shfl_xor_sync(0xffffffffu, q, off);
    }
    float mean = s * (1.f / 192.f);
    float rstd = rsqrtf(q * (1.f / 192.f) - mean * mean + 1e-5f);
    float* dst = g_t + (size_t)row * 192;
#pragma unroll
    for (int j = 0; j < 6; j++) {
        int c = lane + j * 32;
        dst[c] = (v[j] - mean) * rstd * gam[c] + bet[c];
    }
}

// ---------------- generic GEMM (3xTF32, pre-split smem) ----------------
template <int BN>
__global__ void __launch_bounds__(256) k_gemm_tc(const float* __restrict__ A,
                                                 const float* __restrict__ W,
                                                 const float* __restrict__ bias,
                                                 float* __restrict__ C,
                                                 int M, int Nout) {
    constexpr int NT = BN / 16;
    extern __shared__ float smg[];
    float* Ash = smg;
    float* Asl = Ash + 4608;
    float* Wsh = Asl + 4608;
    float* Wsl = Wsh + BN * 36;
    int m0 = blockIdx.x * 128, n0 = blockIdx.y * BN;
    int tid = threadIdx.x, wid = tid >> 5, lane = tid & 31;
    int g = lane >> 2, tcol = lane & 3;
    int wm0 = (wid >> 1) * 32, wn0 = (wid & 1) * (BN / 2);
    float acc[2][NT][4];
#pragma unroll
    for (int a = 0; a < 2; a++)
#pragma unroll
        for (int b = 0; b < NT; b++)
#pragma unroll
            for (int c = 0; c < 4; c++) acc[a][b][c] = 0.f;

    for (int kc = 0; kc < 192; kc += 32) {
#pragma unroll
        for (int i = 0; i < 4; i++) {
            int f = tid + i * 256;
            int row = f >> 3, seg = f & 7;
            float4 v = *(const float4*)(A + (size_t)(m0 + row) * 192 + kc + seg * 4);
            float4 hv, lv;
            split_tf_f(v.x, hv.x, lv.x); split_tf_f(v.y, hv.y, lv.y);
            split_tf_f(v.z, hv.z, lv.z); split_tf_f(v.w, hv.w, lv.w);
            int off = row * 36 + seg * 4;
            *(float4*)(Ash + off) = hv;
            *(float4*)(Asl + off) = lv;
        }
#pragma unroll
        for (int i = 0; i < BN / 32; i++) {
            int f = tid + i * 256;
            int row = f >> 3, seg = f & 7;
            float4 v = *(const float4*)(W + (size_t)(n0 + row) * 192 + kc + seg * 4);
            float4 hv, lv;
            split_tf_f(v.x, hv.x, lv.x); split_tf_f(v.y, hv.y, lv.y);
            split_tf_f(v.z, hv.z, lv.z); split_tf_f(v.w, hv.w, lv.w);
            int off = row * 36 + seg * 4;
            *(float4*)(Wsh + off) = hv;
            *(float4*)(Wsl + off) = lv;
        }
        __syncthreads();
#pragma unroll
        for (int kk = 0; kk < 32; kk += 8) {
            unsigned bh[NT][2], bl[NT][2];
#pragma unroll
            for (int nt = 0; nt < NT; nt++) {
                int wr = (wn0 + nt * 8 + g) * 36;
                bh[nt][0] = __float_as_uint(Wsh[wr + kk + tcol]);
                bl[nt][0] = __float_as_uint(Wsl[wr + kk + tcol]);
                bh[nt][1] = __float_as_uint(Wsh[wr + kk + 4 + tcol]);
                bl[nt][1] = __float_as_uint(Wsl[wr + kk + 4 + tcol]);
            }
#pragma unroll
            for (int mt = 0; mt < 2; mt++) {
                int r = wm0 + mt * 16 + g;
                int ar = r * 36, ar8 = (r + 8) * 36;
                unsigned ah[4], al[4];
                ah[0] = __float_as_uint(Ash[ar + kk + tcol]);
                ah[1] = __float_as_uint(Ash[ar8 + kk + tcol]);
                ah[2] = __float_as_uint(Ash[ar + kk + 4 + tcol]);
                ah[3] = __float_as_uint(Ash[ar8 + kk + 4 + tcol]);
                al[0] = __float_as_uint(Asl[ar + kk + tcol]);
                al[1] = __float_as_uint(Asl[ar8 + kk + tcol]);
                al[2] = __float_as_uint(Asl[ar + kk + 4 + tcol]);
                al[3] = __float_as_uint(Asl[ar8 + kk + 4 + tcol]);
#pragma unroll
                for (int nt = 0; nt < NT; nt++) mma8(acc[mt][nt], al, bh[nt]);
#pragma unroll
                for (int nt = 0; nt < NT; nt++) mma8(acc[mt][nt], ah, bl[nt]);
#pragma unroll
                for (int nt = 0; nt < NT; nt++) mma8(acc[mt][nt], ah, bh[nt]);
            }
        }
        __syncthreads();
    }
#pragma unroll
    for (int mt = 0; mt < 2; mt++)
#pragma unroll
        for (int nt = 0; nt < NT; nt++) {
            int r = m0 + wm0 + mt * 16 + g;
            int cc = n0 + wn0 + nt * 8 + 2 * tcol;
            float b0v = bias[cc], b1v = bias[cc + 1];
            C[(size_t)r * Nout + cc]           = acc[mt][nt][0] + b0v;
            C[(size_t)r * Nout + cc + 1]       = acc[mt][nt][1] + b1v;
            C[(size_t)(r + 8) * Nout + cc]     = acc[mt][nt][2] + b0v;
            C[(size_t)(r + 8) * Nout + cc + 1] = acc[mt][nt][3] + b1v;
        }
}

// ---------------- fused post ----------------
__global__ void k_post(const float* __restrict__ qe, const float* __restrict__ temp,
                       const float* __restrict__ seqscale) {
    int idx = blockIdx.x * 256 + threadIdx.x;
    int g = idx % 24;
    int bn = idx / 24;
    int n = bn & 4095; int b = bn >> 12;
    if (g < 8) {
        int h = g;
        const float4* q4 = (const float4*)(g_qkvs + (size_t)bn * 768 + h * 24);
        float v[24]; float s = 0.f;
#pragma unroll
        for (int i = 0; i < 6; i++) {
            float4 t = q4[i];
            v[4 * i] = t.x; v[4 * i + 1] = t.y; v[4 * i + 2] = t.z; v[4 * i + 3] = t.w;
        }
#pragma unroll
        for (int d = 0; d < 24; d++) s += v[d] * v[d];
        float rn = 1.f / fmaxf(sqrtf(s), 1e-12f);
        float sp = log1pf(expf(temp[h]));
        float ss = seqscale[n];
        size_t ob = ((size_t)(b * 8 + h) * 4096 + n) * 24;
        float qn[24];
        float4* qn4 = (float4*)(g_qn + ob);
        float4* qs4 = (float4*)(g_qs + ob);
#pragma unroll
        for (int i = 0; i < 6; i++) {
            float4 a, c;
            a.x = v[4 * i] * rn;     c.x = (a.x + qe[h * 24 + 4 * i])     * sp * ss;
            a.y = v[4 * i + 1] * rn; c.y = (a.y + qe[h * 24 + 4 * i + 1]) * sp * ss;
            a.z = v[4 * i + 2] * rn; c.z = (a.z + qe[h * 24 + 4 * i + 2]) * sp * ss;
            a.w = v[4 * i + 3] * rn; c.w = (a.w + qe[h * 24 + 4 * i + 3]) * sp * ss;
            qn4[i] = a; qs4[i] = c;
            qn[4 * i] = a.x; qn[4 * i + 1] = a.y; qn[4 * i + 2] = a.z; qn[4 * i + 3] = a.w;
        }
        size_t ob2 = ((size_t)(b * 8 + h) * 4096 + n) * 12;
        const float* ltr = g_lt2 + h * 216;
#pragma unroll
        for (int l = 0; l < 9; l++) {
            float p = 0.f;
#pragma unroll
            for (int d = 0; d < 24; d++) p += qn[d] * ltr[l * 24 + d];
            g_w2[ob2 + l] = p;
        }
    } else {
        int gg = g - 8;
        const float4* src4 = (const float4*)(g_qkvs + (size_t)bn * 768 + 192 + gg * 24);
        float v[24]; float s = 0.f;
#pragma unroll
        for (int i = 0; i < 6; i++) {
            float4 t = src4[i];
            v[4 * i] = t.x; v[4 * i + 1] = t.y; v[4 * i + 2] = t.z; v[4 * i + 3] = t.w;
        }
#pragma unroll
        for (int d = 0; d < 24; d++) s += v[d] * v[d];
        float rn = 1.f;
        if (gg < 8) rn = 1.f / fmaxf(sqrtf(s), 1e-12f);
        size_t ob = ((size_t)(b * 16 + gg) * 4096 + n) * 24;
        float4* dst4 = (float4*)(g_kvmap + ob);
#pragma unroll
        for (int i = 0; i < 6; i++) {
            float4 o;
            o.x = v[4 * i] * rn; o.y = v[4 * i + 1] * rn;
            o.z = v[4 * i + 2] * rn; o.w = v[4 * i + 3] * rn;
            dst4[i] = o;
        }
    }
}

// ---------------- gelu + 4x4 pool + LN ----------------
__global__ void k_pool(const float* __restrict__ ng, const float* __restrict__ nb) {
    __shared__ float r1[192], r2[192];
    int b = blockIdx.y, m = blockIdx.x;
    int c = threadIdx.x;
    int ph = m >> 4, pw = m & 15;
    float acc = 0.f;
#pragma unroll
    for (int i = 0; i < 4; i++)
#pragma unroll
        for (int j = 0; j < 4; j++) {
            int n = (ph * 4 + i) * 64 + pw * 4 + j;
            float v = g_qkvs[((size_t)(b * 4096 + n)) * 768 + 576 + c];
            acc += 0.5f * v * (1.f + erff(v * 0.70710678118654752f));
        }
    acc *= (1.f / 16.f);
    r1[c] = acc; r2[c] = acc * acc;
    __syncthreads();
    if (c < 64) { r1[c] += r1[c + 64] + r1[c + 128]; r2[c] += r2[c + 64] + r2[c + 128]; }
    __syncthreads();
    for (int s2 = 32; s2 > 0; s2 >>= 1) {
        if (c < s2) { r1[c] += r1[c + s2]; r2[c] += r2[c + s2]; }
        __syncthreads();
    }
    float mean = r1[0] * (1.f / 192.f);
    float var = r2[0] * (1.f / 192.f) - mean * mean;
    float rstd = rsqrtf(var + 1e-5f);
    g_pooled[((size_t)(b * 256 + m)) * 192 + c] = (acc - mean) * rstd * ng[c] + nb[c];
}

// ---------------- post pooled kv ----------------
__global__ void k_postkvp() {
    int idx = blockIdx.x * 256 + threadIdx.x;
    int g = idx & 15; int bm = idx >> 4;
    int m = bm & 255; int b = bm >> 8;
    const float4* src4 = (const float4*)(g_kvp + (size_t)bm * 384 + g * 24);
    float v[24]; float s = 0.f;
#pragma unroll
    for (int i = 0; i < 6; i++) {
        float4 t = src4[i];
        v[4 * i] = t.x; v[4 * i + 1] = t.y; v[4 * i + 2] = t.z; v[4 * i + 3] = t.w;
    }
#pragma unroll
    for (int d = 0; d < 24; d++) s += v[d] * v[d];
    if (g < 8) {
        float rn = 1.f / fmaxf(sqrtf(s), 1e-12f);
        float4* dst4 = (float4*)(g_kpn + ((size_t)(b * 8 + g) * 256 + m) * 24);
#pragma unroll
        for (int i = 0; i < 6; i++) {
            float4 o;
            o.x = v[4 * i] * rn; o.y = v[4 * i + 1] * rn;
            o.z = v[4 * i + 2] * rn; o.w = v[4 * i + 3] * rn;
            dst4[i] = o;
        }
    } else {
        float4* dst4 = (float4*)(g_vpn + ((size_t)(b * 8 + g - 8) * 256 + m) * 24);
#pragma unroll
        for (int i = 0; i < 6; i++) {
            float4 o;
            o.x = v[4 * i]; o.y = v[4 * i + 1]; o.z = v[4 * i + 2]; o.w = v[4 * i + 3];
            dst4[i] = o;
        }
    }
}

// ---------------- fused attention (2 queries/warp, no local-K smem, 3 CTAs/SM) ----------------
// smem: skp[m][28] 7168 | svp[d][260] 6240 | slog 16*296=4736 | srpb 16 | slb 16 = 18176 fl (72.7KB)
__global__ void __launch_bounds__(256, 3) k_attn(const int* __restrict__ rel_idx,
                                                 const float* __restrict__ rpb,
                                                 const float* __restrict__ lb) {
    extern __shared__ float sm[];
    float* skp = sm;
    float* svp = skp + 7168;
    float* slog = svp + 6240;
    float* srpb = slog + 4736;
    float* slb = srpb + 16;

    int b = blockIdx.z, h = blockIdx.y;
    int Y0 = (blockIdx.x >> 2) * 16, X0 = (blockIdx.x & 3) * 16;
    int tid = threadIdx.x;

    const float* kbase = g_kvmap + ((size_t)(b * 16 + h) * 4096) * 24;
    const float* vbase = g_kvmap + ((size_t)(b * 16 + 8 + h) * 4096) * 24;
    const float* kp = g_kpn + (size_t)(b * 8 + h) * 256 * 24;
    const float* vp = g_vpn + (size_t)(b * 8 + h) * 256 * 24;
    for (int f = tid; f < 1536; f += 256) {
        int m = f / 6, q = f - m * 6;
        *(float4*)(skp + m * 28 + q * 4) = *(const float4*)(kp + m * 24 + q * 4);
    }
    for (int f = tid; f < 1024; f += 256) {
        int m = f >> 2, d = 24 + (f & 3);
        skp[m * 28 + d] = 0.f;
    }
    for (int idx = tid; idx < 6240; idx += 256) {
        int d = idx / 260, m = idx - d * 260;
        svp[idx] = (m < 256) ? vp[m * 24 + d] : 0.f;
    }
    if (tid < 9) { srpb[tid] = rpb[h * 9 + tid]; slb[tid] = lb[h * 9 + tid]; }
    __syncthreads();

    int w = tid >> 5, ln = tid & 31;
    float* mylogA = slog + w * 296;
    float* mylogB = slog + (8 + w) * 296;
    const unsigned FULL = 0xffffffffu;
    size_t bh4096 = (size_t)(b * 8 + h) * 4096;

    for (int it = 0; it < 16; it++) {
        int qiA = it * 16 + w;
        int qiB = qiA + 8;
        int tyA = qiA >> 4, txA = qiA & 15;
        int tyB = qiB >> 4, txB = qiB & 15;
        int gyA = Y0 + tyA, gxA = X0 + txA;
        int gyB = Y0 + tyB, gxB = X0 + txB;
        int nA = gyA * 64 + gxA, nB = gyB * 64 + gxB;

        float qsA = 0.f, qsB = 0.f;
        if (ln < 24) {
            qsA = g_qs[(bh4096 + nA) * 24 + ln];
            qsB = g_qs[(bh4096 + nB) * 24 + ln];
        }
        float qallA[24], qallB[24];
#pragma unroll
        for (int d = 0; d < 24; d++) {
            qallA[d] = __shfl_sync(FULL, qsA, d);
            qallB[d] = __shfl_sync(FULL, qsB, d);
        }

        // lane-parallel local logits: lanes 0..8 -> A (via LDG), lanes 16..24 -> B
        float w2v = 0.f;
        if (ln < 9) {
            w2v = g_w2[(bh4096 + nA) * 12 + ln];
            int dh = ln / 3 - 1, dw = ln % 3 - 1;
            int ny = gyA + dh, nx = gxA + dw;
            bool lvalid = (ny >= 0) && (ny < 64) && (nx >= 0) && (nx < 64);
            float p1 = -1e30f;
            if (lvalid) {
                const float* krow = kbase + (size_t)(ny * 64 + nx) * 24;
                float4 k0 = *(const float4*)(krow);
                float4 k1 = *(const float4*)(krow + 4);
                float4 k2 = *(const float4*)(krow + 8);
                float4 k3 = *(const float4*)(krow + 12);
                float4 k4 = *(const float4*)(krow + 16);
                float4 k5 = *(const float4*)(krow + 20);
                p1 = srpb[ln]
                   + qallA[0]  * k0.x + qallA[1]  * k0.y + qallA[2]  * k0.z + qallA[3]  * k0.w
                   + qallA[4]  * k1.x + qallA[5]  * k1.y + qallA[6]  * k1.z + qallA[7]  * k1.w
                   + qallA[8]  * k2.x + qallA[9]  * k2.y + qallA[10] * k2.z + qallA[11] * k2.w
                   + qallA[12] * k3.x + qallA[13] * k3.y + qallA[14] * k3.z + qallA[15] * k3.w
                   + qallA[16] * k4.x + qallA[17] * k4.y + qallA[18] * k4.z + qallA[19] * k4.w
                   + qallA[20] * k5.x + qallA[21] * k5.y + qallA[22] * k5.z + qallA[23] * k5.w;
            }
            mylogA[ln] = p1;
        } else if (ln >= 16 && ln < 25) {
            int l = ln - 16;
            w2v = g_w2[(bh4096 + nB) * 12 + l];
            int dh = l / 3 - 1, dw = l % 3 - 1;
            int ny = gyB + dh, nx = gxB + dw;
            bool lvalid = (ny >= 0) && (ny < 64) && (nx >= 0) && (nx < 64);
            float p1 = -1e30f;
            if (lvalid) {
                const float* krow = kbase + (size_t)(ny * 64 + nx) * 24;
                float4 k0 = *(const float4*)(krow);
                float4 k1 = *(const float4*)(krow + 4);
                float4 k2 = *(const float4*)(krow + 8);
                float4 k3 = *(const float4*)(krow + 12);
                float4 k4 = *(const float4*)(krow + 16);
                float4 k5 = *(const float4*)(krow + 20);
                p1 = srpb[l]
                   + qallB[0]  * k0.x + qallB[1]  * k0.y + qallB[2]  * k0.z + qallB[3]  * k0.w
                   + qallB[4]  * k1.x + qallB[5]  * k1.y + qallB[6]  * k1.z + qallB[7]  * k1.w
                   + qallB[8]  * k2.x + qallB[9]  * k2.y + qallB[10] * k2.z + qallB[11] * k2.w
                   + qallB[12] * k3.x + qallB[13] * k3.y + qallB[14] * k3.z + qallB[15] * k3.w
                   + qallB[16] * k4.x + qallB[17] * k4.y + qallB[18] * k4.z + qallB[19] * k4.w
                   + qallB[20] * k5.x + qallB[21] * k5.y + qallB[22] * k5.z + qallB[23] * k5.w;
            }
            mylogB[l] = p1;
        }

        // pool logits: shared K-row load serves both queries
        const int* riA = rel_idx + (size_t)nA * 256;
        const int* riB = rel_idx + (size_t)nB * 256;
#pragma unroll
        for (int bm = 0; bm < 8; bm++) {
            int m = bm * 32 + ln;
            float aA = g_cpb[(size_t)riA[m] * 8 + h];
            float aB = g_cpb[(size_t)riB[m] * 8 + h];
            const float* row = skp + m * 28;
            float4 k0 = *(const float4*)(row);
            float4 k1 = *(const float4*)(row + 4);
            float4 k2 = *(const float4*)(row + 8);
            float4 k3 = *(const float4*)(row + 12);
            float4 k4 = *(const float4*)(row + 16);
            float4 k5 = *(const float4*)(row + 20);
            aA += qallA[0]  * k0.x + qallA[1]  * k0.y + qallA[2]  * k0.z + qallA[3]  * k0.w;
            aB += qallB[0]  * k0.x + qallB[1]  * k0.y + qallB[2]  * k0.z + qallB[3]  * k0.w;
            aA += qallA[4]  * k1.x + qallA[5]  * k1.y + qallA[6]  * k1.z + qallA[7]  * k1.w;
            aB += qallB[4]  * k1.x + qallB[5]  * k1.y + qallB[6]  * k1.z + qallB[7]  * k1.w;
            aA += qallA[8]  * k2.x + qallA[9]  * k2.y + qallA[10] * k2.z + qallA[11] * k2.w;
            aB += qallB[8]  * k2.x + qallB[9]  * k2.y + qallB[10] * k2.z + qallB[11] * k2.w;
            aA += qallA[12] * k3.x + qallA[13] * k3.y + qallA[14] * k3.z + qallA[15] * k3.w;
            aB += qallB[12] * k3.x + qallB[13] * k3.y + qallB[14] * k3.z + qallB[15] * k3.w;
            aA += qallA[16] * k4.x + qallA[17] * k4.y + qallA[18] * k4.z + qallA[19] * k4.w;
            aB += qallB[16] * k4.x + qallB[17] * k4.y + qallB[18] * k4.z + qallB[19] * k4.w;
            aA += qallA[20] * k5.x + qallA[21] * k5.y + qallA[22] * k5.z + qallA[23] * k5.w;
            aB += qallB[20] * k5.x + qallB[21] * k5.y + qallB[22] * k5.z + qallB[23] * k5.w;
            mylogA[32 + m] = aA;
            mylogB[32 + m] = aB;
        }
        __syncwarp();

        // softmax (both queries)
        float mxA = -1e30f, mxB = -1e30f;
#pragma unroll
        for (int j = 0; j < 8; j++) {
            mxA = fmaxf(mxA, mylogA[32 + j * 32 + ln]);
            mxB = fmaxf(mxB, mylogB[32 + j * 32 + ln]);
        }
        if (ln < 9) {
            mxA = fmaxf(mxA, mylogA[ln]);
            mxB = fmaxf(mxB, mylogB[ln]);
        }
#pragma unroll
        for (int off = 16; off > 0; off >>= 1) {
            mxA = fmaxf(mxA, __shfl_xor_sync(FULL, mxA, off));
            mxB = fmaxf(mxB, __shfl_xor_sync(FULL, mxB, off));
        }
        float sumA = 0.f, sumB = 0.f;
#pragma unroll
        for (int j = 0; j < 8; j++) {
            int i = 32 + j * 32 + ln;
            float eA = expf(mylogA[i] - mxA); mylogA[i] = eA; sumA += eA;
            float eB = expf(mylogB[i] - mxB); mylogB[i] = eB; sumB += eB;
        }
        if (ln < 9) {
            float eA = expf(mylogA[ln] - mxA); mylogA[ln] = eA; sumA += eA;
            float eB = expf(mylogB[ln] - mxB); mylogB[ln] = eB; sumB += eB;
        }
#pragma unroll
        for (int off = 16; off > 0; off >>= 1) {
            sumA += __shfl_xor_sync(FULL, sumA, off);
            sumB += __shfl_xor_sync(FULL, sumB, off);
        }
        float invA = 1.f / sumA, invB = 1.f / sumB;
        __syncwarp();
#pragma unroll
        for (int j = 0; j < 8; j++) {
            mylogA[32 + j * 32 + ln] *= invA;
            mylogB[32 + j * 32 + ln] *= invB;
        }
        if (ln < 9)                 mylogA[ln]      = w2v + slb[ln]      + mylogA[ln] * invA;
        else if (ln >= 16 && ln < 25) mylogB[ln - 16] = w2v + slb[ln - 16] + mylogB[ln - 16] * invB;
        __syncwarp();

        if (ln < 24) {
            float aA0 = 0.f, aA1 = 0.f, aB0 = 0.f, aB1 = 0.f;
#pragma unroll
            for (int l = 0; l < 9; l++) {
                int dh = l / 3 - 1, dw = l % 3 - 1;
                int nyA = gyA + dh, nxA = gxA + dw;
                if (nyA >= 0 && nyA < 64 && nxA >= 0 && nxA < 64)
                    aA0 += mylogA[l] * vbase[(size_t)(nyA * 64 + nxA) * 24 + ln];
                int nyB = gyB + dh, nxB = gxB + dw;
                if (nyB >= 0 && nyB < 64 && nxB >= 0 && nxB < 64)
                    aB0 += mylogB[l] * vbase[(size_t)(nyB * 64 + nxB) * 24 + ln];
            }
            const float* vrow = svp + ln * 260;
#pragma unroll
            for (int m = 0; m < 256; m += 8) {
                float4 v0 = *(const float4*)(vrow + m);
                float4 v1 = *(const float4*)(vrow + m + 4);
                float4 wA0 = *(const float4*)(mylogA + 32 + m);
                float4 wA1 = *(const float4*)(mylogA + 36 + m);
                float4 wB0 = *(const float4*)(mylogB + 32 + m);
                float4 wB1 = *(const float4*)(mylogB + 36 + m);
                aA0 += wA0.x * v0.x + wA0.y * v0.y + wA0.z * v0.z + wA0.w * v0.w;
                aB0 += wB0.x * v0.x + wB0.y * v0.y + wB0.z * v0.z + wB0.w * v0.w;
                aA1 += wA1.x * v1.x + wA1.y * v1.y + wA1.z * v1.z + wA1.w * v1.w;
                aB1 += wB1.x * v1.x + wB1.y * v1.y + wB1.z * v1.z + wB1.w * v1.w;
            }
            g_ao[((size_t)(b * 4096 + nA)) * 192 + h * 24 + ln] = aA0 + aA1;
            g_ao[((size_t)(b * 4096 + nB)) * 192 + h * 24 + ln] = aB0 + aB1;
        }
        __syncwarp();
    }
}

// ---------------- final LN + transpose to (B,C,N) ----------------
__global__ void k_lnout(const float* __restrict__ gam, const float* __restrict__ bet,
                        float* __restrict__ out) {
    __shared__ float s[192 * 33];
    __shared__ float red[2][8][32];
    __shared__ float smean[32], srstd[32];
    int b = blockIdx.y, n0 = blockIdx.x * 32;
    int tx = threadIdx.x & 31, ty = threadIdx.x >> 5;
    for (int idx = threadIdx.x; idx < 32 * 192; idx += 256) {
        int i = idx / 192, c = idx - i * 192;
        s[c * 33 + i] = g_tmp[((size_t)(b * 4096 + n0 + i)) * 192 + c];
    }
    __syncthreads();
    float sum = 0.f, sq = 0.f;
    for (int c = ty; c < 192; c += 8) {
        float v = s[c * 33 + tx];
        sum += v; sq += v * v;
    }
    red[0][ty][tx] = sum; red[1][ty][tx] = sq;
    __syncthreads();
    if (ty == 0) {
        float s1 = 0.f, s2 = 0.f;
#pragma unroll
        for (int k = 0; k < 8; k++) { s1 += red[0][k][tx]; s2 += red[1][k][tx]; }
        float m = s1 * (1.f / 192.f);
        float var = s2 * (1.f / 192.f) - m * m;
        smean[tx] = m; srstd[tx] = rsqrtf(var + 1e-5f);
    }
    __syncthreads();
    for (int c = ty; c < 192; c += 8)
        out[(size_t)(b * 192 + c) * 4096 + n0 + tx] =
            (s[c * 33 + tx] - smean[tx]) * srstd[tx] * gam[c] + bet[c];
}

// ---------------- launch ----------------
extern "C" void kernel_launch(void* const* d_in, const int* in_sizes, int n_in,
                              void* d_out, int out_size) {
    const float* x      = (const float*)d_in[0];
    const float* pe_w   = (const float*)d_in[1];
    const float* pe_b   = (const float*)d_in[2];
    const float* pe_ln_g= (const float*)d_in[3];
    const float* pe_ln_b= (const float*)d_in[4];
    const float* q_w    = (const float*)d_in[5];
    const float* q_b    = (const float*)d_in[6];
    const float* kv_w   = (const float*)d_in[7];
    const float* kv_b   = (const float*)d_in[8];
    const float* sr_w   = (const float*)d_in[9];
    const float* sr_b   = (const float*)d_in[10];
    const float* norm_g = (const float*)d_in[11];
    const float* norm_b = (const float*)d_in[12];
    const float* cpb1_w = (const float*)d_in[13];
    const float* cpb1_b = (const float*)d_in[14];
    const float* cpb2_w = (const float*)d_in[15];
    const float* cpb2_b = (const float*)d_in[16];
    const float* rpb    = (const float*)d_in[17];
    const float* lt     = (const float*)d_in[18];
    const float* lb     = (const float*)d_in[19];
    const float* qe     = (const float*)d_in[20];
    const float* temp   = (const float*)d_in[21];
    const float* proj_w = (const float*)d_in[22];
    const float* proj_b = (const float*)d_in[23];
    const float* oln_g  = (const float*)d_in[24];
    const float* oln_b  = (const float*)d_in[25];
    const int*   relidx = (const int*)d_in[26];
    const float* ctab   = (const float*)d_in[27];
    const float* sscale = (const float*)d_in[28];
    float* out = (float*)d_out;

    int T = in_sizes[27] / 2;

    float *p_t, *p_qkvs, *p_pooled, *p_ao, *p_tmp, *p_Wcat, *p_bcat, *p_kvp;
    cudaGetSymbolAddress((void**)&p_t, g_t);
    cudaGetSymbolAddress((void**)&p_qkvs, g_qkvs);
    cudaGetSymbolAddress((void**)&p_pooled, g_pooled);
    cudaGetSymbolAddress((void**)&p_kvp, g_kvp);
    cudaGetSymbolAddress((void**)&p_ao, g_ao);
    cudaGetSymbolAddress((void**)&p_tmp, g_tmp);
    cudaGetSymbolAddress((void**)&p_Wcat, g_Wcat);
    cudaGetSymbolAddress((void**)&p_bcat, g_bcat);

    int attn_smem = 18176 * 4;
    int conv_smem = 14848 * 4;
    int gemm128_smem = (4608 * 2 + 128 * 36 * 2) * 4;
    int gemm64_smem  = (4608 * 2 + 64 * 36 * 2) * 4;

    cudaFuncSetAttribute(k_attn, cudaFuncAttributeMaxDynamicSharedMemorySize, attn_smem);
    cudaFuncSetAttribute(k_conv_tc, cudaFuncAttributeMaxDynamicSharedMemorySize, conv_smem);
    cudaFuncSetAttribute(k_gemm_tc<128>, cudaFuncAttributeMaxDynamicSharedMemorySize, gemm128_smem);
    cudaFuncSetAttribute(k_gemm_tc<64>, cudaFuncAttributeMaxDynamicSharedMemorySize, gemm64_smem);

    k_prep_w<<<576, 256>>>(q_w, q_b, kv_w, kv_b, sr_w, sr_b, lt);
    k_prep_wc<<<1296, 256>>>(pe_w);
    k_prep_cpb<<<(T + 255) / 256, 256>>>(ctab, cpb1_w, cpb1_b, cpb2_w, cpb2_b, T);
    k_conv_tc<<<dim3(128, 3), 256, conv_smem>>>(x, pe_b);
    k_ln_rows<<<2048, 256>>>(pe_ln_g, pe_ln_b);
    k_gemm_tc<128><<<dim3(128, 6), 256, gemm128_smem>>>(p_t, p_Wcat, p_bcat, p_qkvs, 16384, 768);
    k_post<<<1536, 256>>>(qe, temp, sscale);
    k_pool<<<dim3(256, 4), 192>>>(norm_g, norm_b);
    k_gemm_tc<128><<<dim3(8, 3), 256, gemm128_smem>>>(p_pooled, kv_w, kv_b, p_kvp, 1024, 384);
    k_postkvp<<<64, 256>>>();
    k_attn<<<dim3(16, 8, 4), 256, attn_smem>>>(relidx, rpb, lb);
    k_gemm_tc<64><<<dim3(128, 3), 256, gemm64_smem>>>(p_ao, proj_w, proj_b, p_tmp, 16384, 192);
    k_lnout<<<dim3(128, 4), 256>>>(oln_g, oln_b, out);
}

// round 9
// speedup vs baseline: 1.1336x; 1.1336x over previous
#include <cuda_runtime.h>
#include <math.h>
#include <stdint.h>

#define BB 4
#define CC 192
#define NN 4096
#define NHEADS 8
#define HD 24
#define PLENC 256

// ---------------- device scratch ----------------
__device__ __align__(256) float g_xc[BB * NN * CC];
__device__ __align__(256) float g_t[BB * NN * CC];
__device__ __align__(256) float g_qkvs[BB * NN * 768];
__device__ __align__(256) float g_qs[BB * NHEADS * NN * HD];
__device__ __align__(256) float g_kvmap[BB * 16 * NN * HD];
__device__ __align__(256) float g_pooled[BB * PLENC * CC];
__device__ __align__(256) float g_kvp[BB * PLENC * 384];
__device__ __align__(256) float g_kpn[BB * NHEADS * PLENC * HD];
__device__ __align__(256) float g_vpn[BB * NHEADS * PLENC * HD];
__device__ __align__(256) float g_ao[BB * NN * CC];
__device__ __align__(256) float g_tmp[BB * NN * CC];
__device__ __align__(256) float g_Wcat[768 * 192];
__device__ __align__(256) float g_bcat[768];
__device__ __align__(256) float g_cpb[32768 * NHEADS];
__device__ __align__(256) float g_Wc2[1728 * 192];
__device__ __align__(256) float g_lt2[NHEADS * 216];
__device__ __align__(256) float g_w2[BB * NHEADS * NN * 12];

// ---------------- tf32 helpers ----------------
__device__ __forceinline__ unsigned f2tf(float f) {
    unsigned u;
    asm("cvt.rna.tf32.f32 %0, %1;" : "=r"(u) : "f"(f));
    return u;
}
__device__ __forceinline__ void split_tf(float f, unsigned& hi, unsigned& lo) {
    hi = f2tf(f);
    lo = f2tf(f - __uint_as_float(hi));
}
__device__ __forceinline__ void split_tf_f(float f, float& hi, float& lo) {
    unsigned h, l;
    split_tf(f, h, l);
    hi = __uint_as_float(h);
    lo = __uint_as_float(l);
}
__device__ __forceinline__ void mma8(float* d, const unsigned* a, const unsigned* b) {
    asm volatile(
        "mma.sync.aligned.m16n8k8.row.col.f32.tf32.tf32.f32 "
        "{%0,%1,%2,%3}, {%4,%5,%6,%7}, {%8,%9}, {%0,%1,%2,%3};"
        : "+f"(d[0]), "+f"(d[1]), "+f"(d[2]), "+f"(d[3])
        : "r"(a[0]), "r"(a[1]), "r"(a[2]), "r"(a[3]), "r"(b[0]), "r"(b[1]));
}

// ---------------- prep: fused Wcat/bcat/lt2 + conv weight transpose ----------------
__global__ void k_prep(const float* __restrict__ qw, const float* __restrict__ qb,
                       const float* __restrict__ kvw, const float* __restrict__ kvb,
                       const float* __restrict__ srw, const float* __restrict__ srb,
                       const float* __restrict__ lt, const float* __restrict__ w) {
    int idx = blockIdx.x * 256 + threadIdx.x;
    if (idx < 331776) {   // conv weight -> k-major
        int o = idx / 1728;
        int r = idx - o * 1728;
        int c = r / 9, t = r - c * 9;
        g_Wc2[(c * 9 + t) * 192 + o] = w[idx];
    }
    if (idx < 768 * 192) {
        int o = idx / 192, c = idx - o * 192;
        float v;
        if (o < 192)      v = qw[o * 192 + c];
        else if (o < 576) v = kvw[(o - 192) * 192 + c];
        else              v = srw[(o - 576) * 192 + c];
        g_Wcat[idx] = v;
    }
    if (idx < 768) {
        float v;
        if (idx < 192)      v = qb[idx];
        else if (idx < 576) v = kvb[idx - 192];
        else                v = srb[idx - 576];
        g_bcat[idx] = v;
    }
    if (idx < 1728) {
        int h = idx / 216;
        int r = idx - h * 216;
        int l = r / 24, d = r - l * 24;
        g_lt2[idx] = lt[h * 216 + d * 9 + l];
    }
}

__global__ void __launch_bounds__(256) k_prep_cpb(const float* __restrict__ tab,
                           const float* __restrict__ c1w, const float* __restrict__ c1b,
                           const float* __restrict__ c2w, const float* __restrict__ c2b,
                           int T) {
    __shared__ float s1w[1024], s1b[512], s2[512 * 8];
    int tid = threadIdx.x;
#pragma unroll
    for (int i = 0; i < 4; i++) s1w[tid + i * 256] = c1w[tid + i * 256];
#pragma unroll
    for (int i = 0; i < 2; i++) s1b[tid + i * 256] = c1b[tid + i * 256];
#pragma unroll
    for (int i = 0; i < 16; i++) {
        int idx = tid + i * 256;
        int j = idx >> 3, h = idx & 7;
        s2[idx] = c2w[h * 512 + j];
    }
    __syncthreads();
    int t = blockIdx.x * 256 + tid;
    if (t >= T || t >= 32768) return;
    float t0 = tab[2 * t], t1 = tab[2 * t + 1];
    float acc[8];
#pragma unroll
    for (int h = 0; h < 8; h++) acc[h] = 0.f;
    for (int j = 0; j < 512; j++) {
        float hv = fmaxf(t0 * s1w[2 * j] + t1 * s1w[2 * j + 1] + s1b[j], 0.f);
#pragma unroll
        for (int h = 0; h < 8; h++) acc[h] += hv * s2[j * 8 + h];
    }
#pragma unroll
    for (int h = 0; h < 8; h++) g_cpb[t * 8 + h] = acc[h] + c2b[h];
}

// ---------------- conv 3x3 as implicit GEMM (3xTF32 mma, pre-split smem) ----------------
__global__ void __launch_bounds__(256) k_conv_tc(const float* __restrict__ x,
                                                 const float* __restrict__ bias) {
    extern __shared__ float sm[];
    float* s_xh = sm;
    float* s_xl = s_xh + 2240;
    float* s_wh = s_xl + 2240;
    float* s_wl = s_wh + 5184;

    int b = blockIdx.x >> 5;
    int y0 = (blockIdx.x & 31) * 2;
    int ocg = blockIdx.y;
    int tid = threadIdx.x;
    int wid = tid >> 5, lane = tid & 31;
    int g = lane >> 2, tcol = lane & 3;
    int wm0 = (wid >> 1) * 32, wn0 = (wid & 1) * 32;

    float acc[2][4][4];
#pragma unroll
    for (int a = 0; a < 2; a++)
#pragma unroll
        for (int bq = 0; bq < 4; bq++)
#pragma unroll
            for (int c = 0; c < 4; c++) acc[a][bq][c] = 0.f;

    const float* xb = x + (size_t)b * 192 * 4096;

    for (int c0 = 0; c0 < 192; c0 += 8) {
#pragma unroll
        for (int i = 0; i < 2; i++) {
            int f = tid + i * 256;
            int c = f >> 6;
            int rem = f & 63;
            int r = rem >> 4, seg = rem & 15;
            int gy = y0 - 1 + r;
            float4 v = make_float4(0.f, 0.f, 0.f, 0.f);
            if (gy >= 0 && gy < 64)
                v = *(const float4*)(xb + ((size_t)(c0 + c) * 64 + gy) * 64 + seg * 4);
            float4 hv, lv;
            split_tf_f(v.x, hv.x, lv.x); split_tf_f(v.y, hv.y, lv.y);
            split_tf_f(v.z, hv.z, lv.z); split_tf_f(v.w, hv.w, lv.w);
            int off = c * 280 + r * 68 + 1 + seg * 4;
            s_xh[off + 0] = hv.x; s_xh[off + 1] = hv.y; s_xh[off + 2] = hv.z; s_xh[off + 3] = hv.w;
            s_xl[off + 0] = lv.x; s_xl[off + 1] = lv.y; s_xl[off + 2] = lv.z; s_xl[off + 3] = lv.w;
        }
        if (tid < 64) {
            int c = tid >> 3;
            int rr = tid & 7;
            int r = rr >> 1, side = rr & 1;
            int off = c * 280 + r * 68 + (side ? 65 : 0);
            s_xh[off] = 0.f; s_xl[off] = 0.f;
        }
#pragma unroll
        for (int i = 0; i < 5; i++) {
            int f = tid + i * 256;
            if (f < 1152) {
                int krow = f >> 4, seg = f & 15;
                float4 wv = *(const float4*)(g_Wc2 + ((size_t)(c0 * 9) + krow) * 192 + ocg * 64 + seg * 4);
                float4 hv, lv;
                split_tf_f(wv.x, hv.x, lv.x); split_tf_f(wv.y, hv.y, lv.y);
                split_tf_f(wv.z, hv.z, lv.z); split_tf_f(wv.w, hv.w, lv.w);
                int off = krow * 72 + seg * 4;
                *(float4*)(s_wh + off) = hv;
                *(float4*)(s_wl + off) = lv;
            }
        }
        __syncthreads();

#pragma unroll
        for (int t = 0; t < 9; t++) {
            int dh = t / 3, dw = t - dh * 3;
            unsigned bh[4][2], bl[4][2];
#pragma unroll
            for (int nt = 0; nt < 4; nt++) {
                int o = wn0 + nt * 8 + g;
                int kr0 = (tcol * 9 + t) * 72 + o;
                int kr1 = ((tcol + 4) * 9 + t) * 72 + o;
                bh[nt][0] = __float_as_uint(s_wh[kr0]);
                bl[nt][0] = __float_as_uint(s_wl[kr0]);
                bh[nt][1] = __float_as_uint(s_wh[kr1]);
                bl[nt][1] = __float_as_uint(s_wl[kr1]);
            }
#pragma unroll
            for (int mt = 0; mt < 2; mt++) {
                int mbase = wm0 + mt * 16;
                int rA = (mbase >> 6) + dh;
                int col0 = (mbase & 63) + g + dw;
                int base0 = tcol * 280 + rA * 68 + col0;
                int base1 = (tcol + 4) * 280 + rA * 68 + col0;
                unsigned ah[4], al[4];
                ah[0] = __float_as_uint(s_xh[base0]);
                ah[1] = __float_as_uint(s_xh[base0 + 8]);
                ah[2] = __float_as_uint(s_xh[base1]);
                ah[3] = __float_as_uint(s_xh[base1 + 8]);
                al[0] = __float_as_uint(s_xl[base0]);
                al[1] = __float_as_uint(s_xl[base0 + 8]);
                al[2] = __float_as_uint(s_xl[base1]);
                al[3] = __float_as_uint(s_xl[base1 + 8]);
#pragma unroll
                for (int nt = 0; nt < 4; nt++) {
                    mma8(acc[mt][nt], al, bh[nt]);
                    mma8(acc[mt][nt], ah, bl[nt]);
                    mma8(acc[mt][nt], ah, bh[nt]);
                }
            }
        }
        __syncthreads();
    }
    const float* bb = bias + ocg * 64;
    size_t rowbase = (size_t)b * 4096 + (size_t)y0 * 64;
#pragma unroll
    for (int mt = 0; mt < 2; mt++) {
#pragma unroll
        for (int nt = 0; nt < 4; nt++) {
            int r0 = wm0 + mt * 16 + g;
            int cc = wn0 + nt * 8 + 2 * tcol;
            float b0v = bb[cc], b1v = bb[cc + 1];
            float* o0 = g_xc + (rowbase + r0) * 192 + ocg * 64 + cc;
            o0[0] = acc[mt][nt][0] + b0v;
            o0[1] = acc[mt][nt][1] + b1v;
            float* o1 = g_xc + (rowbase + r0 + 8) * 192 + ocg * 64 + cc;
            o1[0] = acc[mt][nt][2] + b0v;
            o1[1] = acc[mt][nt][3] + b1v;
        }
    }
}

// ---------------- row LN ----------------
__global__ void k_ln_rows(const float* __restrict__ gam, const float* __restrict__ bet) {
    int row = blockIdx.x * 8 + (threadIdx.x >> 5);
    int lane = threadIdx.x & 31;
    const float* src = g_xc + (size_t)row * 192;
    float v[6];
    float s = 0.f, q = 0.f;
#pragma unroll
    for (int j = 0; j < 6; j++) {
        v[j] = src[lane + j * 32];
        s += v[j]; q += v[j] * v[j];
    }
#pragma unroll
    for (int off = 16; off; off >>= 1) {
        s += __shfl_xor_sync(0xffffffffu, s, off);
        q += __shfl_xor_sync(0xffffffffu, q, off);
    }
    float mean = s * (1.f / 192.f);
    float rstd = rsqrtf(q * (1.f / 192.f) - mean * mean + 1e-5f);
    float* dst = g_t + (size_t)row * 192;
#pragma unroll
    for (int j = 0; j < 6; j++) {
        int c = lane + j * 32;
        dst[c] = (v[j] - mean) * rstd * gam[c] + bet[c];
    }
}

// ---------------- generic GEMM (3xTF32, pre-split smem) ----------------
template <int BN>
__global__ void __launch_bounds__(256) k_gemm_tc(const float* __restrict__ A,
                                                 const float* __restrict__ W,
                                                 const float* __restrict__ bias,
                                                 float* __restrict__ C,
                                                 int M, int Nout) {
    constexpr int NT = BN / 16;
    extern __shared__ float smg[];
    float* Ash = smg;
    float* Asl = Ash + 4608;
    float* Wsh = Asl + 4608;
    float* Wsl = Wsh + BN * 36;
    int m0 = blockIdx.x * 128, n0 = blockIdx.y * BN;
    int tid = threadIdx.x, wid = tid >> 5, lane = tid & 31;
    int g = lane >> 2, tcol = lane & 3;
    int wm0 = (wid >> 1) * 32, wn0 = (wid & 1) * (BN / 2);
    float acc[2][NT][4];
#pragma unroll
    for (int a = 0; a < 2; a++)
#pragma unroll
        for (int b = 0; b < NT; b++)
#pragma unroll
            for (int c = 0; c < 4; c++) acc[a][b][c] = 0.f;

    for (int kc = 0; kc < 192; kc += 32) {
#pragma unroll
        for (int i = 0; i < 4; i++) {
            int f = tid + i * 256;
            int row = f >> 3, seg = f & 7;
            float4 v = *(const float4*)(A + (size_t)(m0 + row) * 192 + kc + seg * 4);
            float4 hv, lv;
            split_tf_f(v.x, hv.x, lv.x); split_tf_f(v.y, hv.y, lv.y);
            split_tf_f(v.z, hv.z, lv.z); split_tf_f(v.w, hv.w, lv.w);
            int off = row * 36 + seg * 4;
            *(float4*)(Ash + off) = hv;
            *(float4*)(Asl + off) = lv;
        }
#pragma unroll
        for (int i = 0; i < BN / 32; i++) {
            int f = tid + i * 256;
            int row = f >> 3, seg = f & 7;
            float4 v = *(const float4*)(W + (size_t)(n0 + row) * 192 + kc + seg * 4);
            float4 hv, lv;
            split_tf_f(v.x, hv.x, lv.x); split_tf_f(v.y, hv.y, lv.y);
            split_tf_f(v.z, hv.z, lv.z); split_tf_f(v.w, hv.w, lv.w);
            int off = row * 36 + seg * 4;
            *(float4*)(Wsh + off) = hv;
            *(float4*)(Wsl + off) = lv;
        }
        __syncthreads();
#pragma unroll
        for (int kk = 0; kk < 32; kk += 8) {
            unsigned bh[NT][2], bl[NT][2];
#pragma unroll
            for (int nt = 0; nt < NT; nt++) {
                int wr = (wn0 + nt * 8 + g) * 36;
                bh[nt][0] = __float_as_uint(Wsh[wr + kk + tcol]);
                bl[nt][0] = __float_as_uint(Wsl[wr + kk + tcol]);
                bh[nt][1] = __float_as_uint(Wsh[wr + kk + 4 + tcol]);
                bl[nt][1] = __float_as_uint(Wsl[wr + kk + 4 + tcol]);
            }
#pragma unroll
            for (int mt = 0; mt < 2; mt++) {
                int r = wm0 + mt * 16 + g;
                int ar = r * 36, ar8 = (r + 8) * 36;
                unsigned ah[4], al[4];
                ah[0] = __float_as_uint(Ash[ar + kk + tcol]);
                ah[1] = __float_as_uint(Ash[ar8 + kk + tcol]);
                ah[2] = __float_as_uint(Ash[ar + kk + 4 + tcol]);
                ah[3] = __float_as_uint(Ash[ar8 + kk + 4 + tcol]);
                al[0] = __float_as_uint(Asl[ar + kk + tcol]);
                al[1] = __float_as_uint(Asl[ar8 + kk + tcol]);
                al[2] = __float_as_uint(Asl[ar + kk + 4 + tcol]);
                al[3] = __float_as_uint(Asl[ar8 + kk + 4 + tcol]);
#pragma unroll
                for (int nt = 0; nt < NT; nt++) {
                    mma8(acc[mt][nt], al, bh[nt]);
                    mma8(acc[mt][nt], ah, bl[nt]);
                    mma8(acc[mt][nt], ah, bh[nt]);
                }
            }
        }
        __syncthreads();
    }
#pragma unroll
    for (int mt = 0; mt < 2; mt++)
#pragma unroll
        for (int nt = 0; nt < NT; nt++) {
            int r = m0 + wm0 + mt * 16 + g;
            int cc = n0 + wn0 + nt * 8 + 2 * tcol;
            float b0v = bias[cc], b1v = bias[cc + 1];
            C[(size_t)r * Nout + cc]           = acc[mt][nt][0] + b0v;
            C[(size_t)r * Nout + cc + 1]       = acc[mt][nt][1] + b1v;
            C[(size_t)(r + 8) * Nout + cc]     = acc[mt][nt][2] + b0v;
            C[(size_t)(r + 8) * Nout + cc + 1] = acc[mt][nt][3] + b1v;
        }
}

// ---------------- fused post: q l2norm/scale (+ qn.lt) + kv l2norm/relayout ----------------
__global__ void k_post(const float* __restrict__ qe, const float* __restrict__ temp,
                       const float* __restrict__ seqscale) {
    int idx = blockIdx.x * 256 + threadIdx.x;
    int g = idx % 24;
    int bn = idx / 24;
    int n = bn & 4095; int b = bn >> 12;
    if (g < 8) {
        int h = g;
        const float4* q4 = (const float4*)(g_qkvs + (size_t)bn * 768 + h * 24);
        float v[24]; float s = 0.f;
#pragma unroll
        for (int i = 0; i < 6; i++) {
            float4 t = q4[i];
            v[4 * i] = t.x; v[4 * i + 1] = t.y; v[4 * i + 2] = t.z; v[4 * i + 3] = t.w;
        }
#pragma unroll
        for (int d = 0; d < 24; d++) s += v[d] * v[d];
        float rn = 1.f / fmaxf(sqrtf(s), 1e-12f);
        float sp = log1pf(expf(temp[h]));
        float ss = seqscale[n];
        size_t ob = ((size_t)(b * 8 + h) * 4096 + n) * 24;
        float qn[24];
        float4* qs4 = (float4*)(g_qs + ob);
#pragma unroll
        for (int i = 0; i < 6; i++) {
            float4 c;
            float a0 = v[4 * i] * rn, a1 = v[4 * i + 1] * rn;
            float a2 = v[4 * i + 2] * rn, a3 = v[4 * i + 3] * rn;
            c.x = (a0 + qe[h * 24 + 4 * i])     * sp * ss;
            c.y = (a1 + qe[h * 24 + 4 * i + 1]) * sp * ss;
            c.z = (a2 + qe[h * 24 + 4 * i + 2]) * sp * ss;
            c.w = (a3 + qe[h * 24 + 4 * i + 3]) * sp * ss;
            qs4[i] = c;
            qn[4 * i] = a0; qn[4 * i + 1] = a1; qn[4 * i + 2] = a2; qn[4 * i + 3] = a3;
        }
        size_t ob2 = ((size_t)(b * 8 + h) * 4096 + n) * 12;
        const float* ltr = g_lt2 + h * 216;
#pragma unroll
        for (int l = 0; l < 9; l++) {
            float p = 0.f;
#pragma unroll
            for (int d = 0; d < 24; d++) p += qn[d] * ltr[l * 24 + d];
            g_w2[ob2 + l] = p;
        }
    } else {
        int gg = g - 8;
        const float4* src4 = (const float4*)(g_qkvs + (size_t)bn * 768 + 192 + gg * 24);
        float v[24]; float s = 0.f;
#pragma unroll
        for (int i = 0; i < 6; i++) {
            float4 t = src4[i];
            v[4 * i] = t.x; v[4 * i + 1] = t.y; v[4 * i + 2] = t.z; v[4 * i + 3] = t.w;
        }
#pragma unroll
        for (int d = 0; d < 24; d++) s += v[d] * v[d];
        float rn = 1.f;
        if (gg < 8) rn = 1.f / fmaxf(sqrtf(s), 1e-12f);
        size_t ob = ((size_t)(b * 16 + gg) * 4096 + n) * 24;
        float4* dst4 = (float4*)(g_kvmap + ob);
#pragma unroll
        for (int i = 0; i < 6; i++) {
            float4 o;
            o.x = v[4 * i] * rn; o.y = v[4 * i + 1] * rn;
            o.z = v[4 * i + 2] * rn; o.w = v[4 * i + 3] * rn;
            dst4[i] = o;
        }
    }
}

// ---------------- gelu + 4x4 pool + LN ----------------
__global__ void k_pool(const float* __restrict__ ng, const float* __restrict__ nb) {
    __shared__ float r1[192], r2[192];
    int b = blockIdx.y, m = blockIdx.x;
    int c = threadIdx.x;
    int ph = m >> 4, pw = m & 15;
    float acc = 0.f;
#pragma unroll
    for (int i = 0; i < 4; i++)
#pragma unroll
        for (int j = 0; j < 4; j++) {
            int n = (ph * 4 + i) * 64 + pw * 4 + j;
            float v = g_qkvs[((size_t)(b * 4096 + n)) * 768 + 576 + c];
            acc += 0.5f * v * (1.f + erff(v * 0.70710678118654752f));
        }
    acc *= (1.f / 16.f);
    r1[c] = acc; r2[c] = acc * acc;
    __syncthreads();
    if (c < 64) { r1[c] += r1[c + 64] + r1[c + 128]; r2[c] += r2[c + 64] + r2[c + 128]; }
    __syncthreads();
    for (int s2 = 32; s2 > 0; s2 >>= 1) {
        if (c < s2) { r1[c] += r1[c + s2]; r2[c] += r2[c + s2]; }
        __syncthreads();
    }
    float mean = r1[0] * (1.f / 192.f);
    float var = r2[0] * (1.f / 192.f) - mean * mean;
    float rstd = rsqrtf(var + 1e-5f);
    g_pooled[((size_t)(b * 256 + m)) * 192 + c] = (acc - mean) * rstd * ng[c] + nb[c];
}

// ---------------- post pooled kv ----------------
__global__ void k_postkvp() {
    int idx = blockIdx.x * 256 + threadIdx.x;
    int g = idx & 15; int bm = idx >> 4;
    int m = bm & 255; int b = bm >> 8;
    const float4* src4 = (const float4*)(g_kvp + (size_t)bm * 384 + g * 24);
    float v[24]; float s = 0.f;
#pragma unroll
    for (int i = 0; i < 6; i++) {
        float4 t = src4[i];
        v[4 * i] = t.x; v[4 * i + 1] = t.y; v[4 * i + 2] = t.z; v[4 * i + 3] = t.w;
    }
#pragma unroll
    for (int d = 0; d < 24; d++) s += v[d] * v[d];
    if (g < 8) {
        float rn = 1.f / fmaxf(sqrtf(s), 1e-12f);
        float4* dst4 = (float4*)(g_kpn + ((size_t)(b * 8 + g) * 256 + m) * 24);
#pragma unroll
        for (int i = 0; i < 6; i++) {
            float4 o;
            o.x = v[4 * i] * rn; o.y = v[4 * i + 1] * rn;
            o.z = v[4 * i + 2] * rn; o.w = v[4 * i + 3] * rn;
            dst4[i] = o;
        }
    } else {
        float4* dst4 = (float4*)(g_vpn + ((size_t)(b * 8 + g - 8) * 256 + m) * 24);
#pragma unroll
        for (int i = 0; i < 6; i++) {
            float4 o;
            o.x = v[4 * i]; o.y = v[4 * i + 1]; o.z = v[4 * i + 2]; o.w = v[4 * i + 3];
            dst4[i] = o;
        }
    }
}

// ---------------- fused attention (2 queries per warp per iteration) ----------------
// smem: sk 7776 | skp[m][28] 7168 | svp[d][260] 6240 | slog 16*296=4736 | srpb 16 | slb 16
__global__ void __launch_bounds__(256) k_attn(const int* __restrict__ rel_idx,
                                              const float* __restrict__ rpb,
                                              const float* __restrict__ lb) {
    extern __shared__ float sm[];
    float* sk  = sm;
    float* skp = sk + 7776;
    float* svp = skp + 7168;
    float* slog = svp + 6240;
    float* srpb = slog + 4736;
    float* slb = srpb + 16;

    int b = blockIdx.z, h = blockIdx.y;
    int Y0 = (blockIdx.x >> 2) * 16, X0 = (blockIdx.x & 3) * 16;
    int tid = threadIdx.x;

    const float* kbase = g_kvmap + ((size_t)(b * 16 + h) * 4096) * 24;
    const float* vbase = g_kvmap + ((size_t)(b * 16 + 8 + h) * 4096) * 24;
    for (int idx = tid; idx < 7776; idx += 256) {
        int d = idx % 24; int r = idx / 24;
        int xx = r % 18;  int yy = r / 18;
        int gy = Y0 - 1 + yy, gx = X0 - 1 + xx;
        float kv = 0.f;
        if (gy >= 0 && gy < 64 && gx >= 0 && gx < 64)
            kv = kbase[(size_t)(gy * 64 + gx) * 24 + d];
        sk[idx] = kv;
    }
    const float* kp = g_kpn + (size_t)(b * 8 + h) * 256 * 24;
    const float* vp = g_vpn + (size_t)(b * 8 + h) * 256 * 24;
    for (int f = tid; f < 1536; f += 256) {
        int m = f / 6, q = f - m * 6;
        *(float4*)(skp + m * 28 + q * 4) = *(const float4*)(kp + m * 24 + q * 4);
    }
    for (int f = tid; f < 1024; f += 256) {
        int m = f >> 2, d = 24 + (f & 3);
        skp[m * 28 + d] = 0.f;
    }
    for (int idx = tid; idx < 6240; idx += 256) {
        int d = idx / 260, m = idx - d * 260;
        svp[idx] = (m < 256) ? vp[m * 24 + d] : 0.f;
    }
    if (tid < 9) { srpb[tid] = rpb[h * 9 + tid]; slb[tid] = lb[h * 9 + tid]; }
    __syncthreads();

    int w = tid >> 5, ln = tid & 31;
    float* mylogA = slog + w * 296;
    float* mylogB = slog + (8 + w) * 296;
    const unsigned FULL = 0xffffffffu;
    size_t bh4096 = (size_t)(b * 8 + h) * 4096;

    for (int it = 0; it < 16; it++) {
        int qiA = it * 16 + w;
        int qiB = qiA + 8;
        int tyA = qiA >> 4, txA = qiA & 15;
        int tyB = qiB >> 4, txB = qiB & 15;
        int gyA = Y0 + tyA, gxA = X0 + txA;
        int gyB = Y0 + tyB, gxB = X0 + txB;
        int nA = gyA * 64 + gxA, nB = gyB * 64 + gxB;

        float qsA = 0.f, qsB = 0.f;
        if (ln < 24) {
            qsA = g_qs[(bh4096 + nA) * 24 + ln];
            qsB = g_qs[(bh4096 + nB) * 24 + ln];
        }
        float qallA[24], qallB[24];
#pragma unroll
        for (int d = 0; d < 24; d++) {
            qallA[d] = __shfl_sync(FULL, qsA, d);
            qallB[d] = __shfl_sync(FULL, qsB, d);
        }

        // lane-parallel local logits: lanes 0..8 -> A, lanes 16..24 -> B
        float w2v = 0.f;
        if (ln < 9) {
            w2v = g_w2[(bh4096 + nA) * 12 + ln];
            int dh = ln / 3 - 1, dw = ln % 3 - 1;
            bool lvalid = (gyA + dh >= 0) && (gyA + dh < 64) && (gxA + dw >= 0) && (gxA + dw < 64);
            const float* krow = sk + ((tyA + 1 + dh) * 18 + (txA + 1 + dw)) * 24;
            float4 k0 = *(const float4*)(krow);
            float4 k1 = *(const float4*)(krow + 4);
            float4 k2 = *(const float4*)(krow + 8);
            float4 k3 = *(const float4*)(krow + 12);
            float4 k4 = *(const float4*)(krow + 16);
            float4 k5 = *(const float4*)(krow + 20);
            float p1 = qallA[0]  * k0.x + qallA[1]  * k0.y + qallA[2]  * k0.z + qallA[3]  * k0.w
                     + qallA[4]  * k1.x + qallA[5]  * k1.y + qallA[6]  * k1.z + qallA[7]  * k1.w
                     + qallA[8]  * k2.x + qallA[9]  * k2.y + qallA[10] * k2.z + qallA[11] * k2.w
                     + qallA[12] * k3.x + qallA[13] * k3.y + qallA[14] * k3.z + qallA[15] * k3.w
                     + qallA[16] * k4.x + qallA[17] * k4.y + qallA[18] * k4.z + qallA[19] * k4.w
                     + qallA[20] * k5.x + qallA[21] * k5.y + qallA[22] * k5.z + qallA[23] * k5.w;
            mylogA[ln] = lvalid ? (p1 + srpb[ln]) : -1e30f;
        } else if (ln >= 16 && ln < 25) {
            int l = ln - 16;
            w2v = g_w2[(bh4096 + nB) * 12 + l];
            int dh = l / 3 - 1, dw = l % 3 - 1;
            bool lvalid = (gyB + dh >= 0) && (gyB + dh < 64) && (gxB + dw >= 0) && (gxB + dw < 64);
            const float* krow = sk + ((tyB + 1 + dh) * 18 + (txB + 1 + dw)) * 24;
            float4 k0 = *(const float4*)(krow);
            float4 k1 = *(const float4*)(krow + 4);
            float4 k2 = *(const float4*)(krow + 8);
            float4 k3 = *(const float4*)(krow + 12);
            float4 k4 = *(const float4*)(krow + 16);
            float4 k5 = *(const float4*)(krow + 20);
            float p1 = qallB[0]  * k0.x + qallB[1]  * k0.y + qallB[2]  * k0.z + qallB[3]  * k0.w
                     + qallB[4]  * k1.x + qallB[5]  * k1.y + qallB[6]  * k1.z + qallB[7]  * k1.w
                     + qallB[8]  * k2.x + qallB[9]  * k2.y + qallB[10] * k2.z + qallB[11] * k2.w
                     + qallB[12] * k3.x + qallB[13] * k3.y + qallB[14] * k3.z + qallB[15] * k3.w
                     + qallB[16] * k4.x + qallB[17] * k4.y + qallB[18] * k4.z + qallB[19] * k4.w
                     + qallB[20] * k5.x + qallB[21] * k5.y + qallB[22] * k5.z + qallB[23] * k5.w;
            mylogB[l] = lvalid ? (p1 + srpb[l]) : -1e30f;
        }

        // pool logits: shared K-row load serves both queries
        const int* riA = rel_idx + (size_t)nA * 256;
        const int* riB = rel_idx + (size_t)nB * 256;
#pragma unroll
        for (int bm = 0; bm < 8; bm++) {
            int m = bm * 32 + ln;
            float aA = g_cpb[(size_t)riA[m] * 8 + h];
            float aB = g_cpb[(size_t)riB[m] * 8 + h];
            const float* row = skp + m * 28;
            float4 k0 = *(const float4*)(row);
            float4 k1 = *(const float4*)(row + 4);
            float4 k2 = *(const float4*)(row + 8);
            float4 k3 = *(const float4*)(row + 12);
            float4 k4 = *(const float4*)(row + 16);
            float4 k5 = *(const float4*)(row + 20);
            aA += qallA[0]  * k0.x + qallA[1]  * k0.y + qallA[2]  * k0.z + qallA[3]  * k0.w;
            aB += qallB[0]  * k0.x + qallB[1]  * k0.y + qallB[2]  * k0.z + qallB[3]  * k0.w;
            aA += qallA[4]  * k1.x + qallA[5]  * k1.y + qallA[6]  * k1.z + qallA[7]  * k1.w;
            aB += qallB[4]  * k1.x + qallB[5]  * k1.y + qallB[6]  * k1.z + qallB[7]  * k1.w;
            aA += qallA[8]  * k2.x + qallA[9]  * k2.y + qallA[10] * k2.z + qallA[11] * k2.w;
            aB += qallB[8]  * k2.x + qallB[9]  * k2.y + qallB[10] * k2.z + qallB[11] * k2.w;
            aA += qallA[12] * k3.x + qallA[13] * k3.y + qallA[14] * k3.z + qallA[15] * k3.w;
            aB += qallB[12] * k3.x + qallB[13] * k3.y + qallB[14] * k3.z + qallB[15] * k3.w;
            aA += qallA[16] * k4.x + qallA[17] * k4.y + qallA[18] * k4.z + qallA[19] * k4.w;
            aB += qallB[16] * k4.x + qallB[17] * k4.y + qallB[18] * k4.z + qallB[19] * k4.w;
            aA += qallA[20] * k5.x + qallA[21] * k5.y + qallA[22] * k5.z + qallA[23] * k5.w;
            aB += qallB[20] * k5.x + qallB[21] * k5.y + qallB[22] * k5.z + qallB[23] * k5.w;
            mylogA[32 + m] = aA;
            mylogB[32 + m] = aB;
        }
        __syncwarp();

        // softmax (both queries)
        float mxA = -1e30f, mxB = -1e30f;
#pragma unroll
        for (int j = 0; j < 8; j++) {
            mxA = fmaxf(mxA, mylogA[32 + j * 32 + ln]);
            mxB = fmaxf(mxB, mylogB[32 + j * 32 + ln]);
        }
        if (ln < 9) {
            mxA = fmaxf(mxA, mylogA[ln]);
            mxB = fmaxf(mxB, mylogB[ln]);
        }
#pragma unroll
        for (int off = 16; off > 0; off >>= 1) {
            mxA = fmaxf(mxA, __shfl_xor_sync(FULL, mxA, off));
            mxB = fmaxf(mxB, __shfl_xor_sync(FULL, mxB, off));
        }
        float sumA = 0.f, sumB = 0.f;
#pragma unroll
        for (int j = 0; j < 8; j++) {
            int i = 32 + j * 32 + ln;
            float eA = expf(mylogA[i] - mxA); mylogA[i] = eA; sumA += eA;
            float eB = expf(mylogB[i] - mxB); mylogB[i] = eB; sumB += eB;
        }
        if (ln < 9) {
            float eA = expf(mylogA[ln] - mxA); mylogA[ln] = eA; sumA += eA;
            float eB = expf(mylogB[ln] - mxB); mylogB[ln] = eB; sumB += eB;
        }
#pragma unroll
        for (int off = 16; off > 0; off >>= 1) {
            sumA += __shfl_xor_sync(FULL, sumA, off);
            sumB += __shfl_xor_sync(FULL, sumB, off);
        }
        float invA = 1.f / sumA, invB = 1.f / sumB;
        __syncwarp();
#pragma unroll
        for (int j = 0; j < 8; j++) {
            mylogA[32 + j * 32 + ln] *= invA;
            mylogB[32 + j * 32 + ln] *= invB;
        }
        if (ln < 9)                 mylogA[ln]      = w2v + slb[ln]      + mylogA[ln] * invA;
        else if (ln >= 16 && ln < 25) mylogB[ln - 16] = w2v + slb[ln - 16] + mylogB[ln - 16] * invB;
        __syncwarp();

        if (ln < 24) {
            float aA0 = 0.f, aA1 = 0.f, aB0 = 0.f, aB1 = 0.f;
            // local AV via guarded LDG (invalid taps contribute 0 per zero-pad semantics)
#pragma unroll
            for (int l = 0; l < 9; l++) {
                int dh = l / 3 - 1, dw = l % 3 - 1;
                int nyA = gyA + dh, nxA = gxA + dw;
                if (nyA >= 0 && nyA < 64 && nxA >= 0 && nxA < 64)
                    aA0 += mylogA[l] * vbase[(size_t)(nyA * 64 + nxA) * 24 + ln];
                int nyB = gyB + dh, nxB = gxB + dw;
                if (nyB >= 0 && nyB < 64 && nxB >= 0 && nxB < 64)
                    aB0 += mylogB[l] * vbase[(size_t)(nyB * 64 + nxB) * 24 + ln];
            }
            const float* vrow = svp + ln * 260;
#pragma unroll
            for (int m = 0; m < 256; m += 8) {
                float4 v0 = *(const float4*)(vrow + m);
                float4 v1 = *(const float4*)(vrow + m + 4);
                float4 wA0 = *(const float4*)(mylogA + 32 + m);
                float4 wA1 = *(const float4*)(mylogA + 36 + m);
                float4 wB0 = *(const float4*)(mylogB + 32 + m);
                float4 wB1 = *(const float4*)(mylogB + 36 + m);
                aA0 += wA0.x * v0.x + wA0.y * v0.y + wA0.z * v0.z + wA0.w * v0.w;
                aB0 += wB0.x * v0.x + wB0.y * v0.y + wB0.z * v0.z + wB0.w * v0.w;
                aA1 += wA1.x * v1.x + wA1.y * v1.y + wA1.z * v1.z + wA1.w * v1.w;
                aB1 += wB1.x * v1.x + wB1.y * v1.y + wB1.z * v1.z + wB1.w * v1.w;
            }
            g_ao[((size_t)(b * 4096 + nA)) * 192 + h * 24 + ln] = aA0 + aA1;
            g_ao[((size_t)(b * 4096 + nB)) * 192 + h * 24 + ln] = aB0 + aB1;
        }
        __syncwarp();
    }
}

// ---------------- final LN + transpose to (B,C,N) ----------------
__global__ void k_lnout(const float* __restrict__ gam, const float* __restrict__ bet,
                        float* __restrict__ out) {
    __shared__ float s[192 * 33];
    __shared__ float red[2][8][32];
    __shared__ float smean[32], srstd[32];
    int b = blockIdx.y, n0 = blockIdx.x * 32;
    int tx = threadIdx.x & 31, ty = threadIdx.x >> 5;
    for (int idx = threadIdx.x; idx < 32 * 192; idx += 256) {
        int i = idx / 192, c = idx - i * 192;
        s[c * 33 + i] = g_tmp[((size_t)(b * 4096 + n0 + i)) * 192 + c];
    }
    __syncthreads();
    float sum = 0.f, sq = 0.f;
    for (int c = ty; c < 192; c += 8) {
        float v = s[c * 33 + tx];
        sum += v; sq += v * v;
    }
    red[0][ty][tx] = sum; red[1][ty][tx] = sq;
    __syncthreads();
    if (ty == 0) {
        float s1 = 0.f, s2 = 0.f;
#pragma unroll
        for (int k = 0; k < 8; k++) { s1 += red[0][k][tx]; s2 += red[1][k][tx]; }
        float m = s1 * (1.f / 192.f);
        float var = s2 * (1.f / 192.f) - m * m;
        smean[tx] = m; srstd[tx] = rsqrtf(var + 1e-5f);
    }
    __syncthreads();
    for (int c = ty; c < 192; c += 8)
        out[(size_t)(b * 192 + c) * 4096 + n0 + tx] =
            (s[c * 33 + tx] - smean[tx]) * srstd[tx] * gam[c] + bet[c];
}

// ---------------- launch ----------------
extern "C" void kernel_launch(void* const* d_in, const int* in_sizes, int n_in,
                              void* d_out, int out_size) {
    const float* x      = (const float*)d_in[0];
    const float* pe_w   = (const float*)d_in[1];
    const float* pe_b   = (const float*)d_in[2];
    const float* pe_ln_g= (const float*)d_in[3];
    const float* pe_ln_b= (const float*)d_in[4];
    const float* q_w    = (const float*)d_in[5];
    const float* q_b    = (const float*)d_in[6];
    const float* kv_w   = (const float*)d_in[7];
    const float* kv_b   = (const float*)d_in[8];
    const float* sr_w   = (const float*)d_in[9];
    const float* sr_b   = (const float*)d_in[10];
    const float* norm_g = (const float*)d_in[11];
    const float* norm_b = (const float*)d_in[12];
    const float* cpb1_w = (const float*)d_in[13];
    const float* cpb1_b = (const float*)d_in[14];
    const float* cpb2_w = (const float*)d_in[15];
    const float* cpb2_b = (const float*)d_in[16];
    const float* rpb    = (const float*)d_in[17];
    const float* lt     = (const float*)d_in[18];
    const float* lb     = (const float*)d_in[19];
    const float* qe     = (const float*)d_in[20];
    const float* temp   = (const float*)d_in[21];
    const float* proj_w = (const float*)d_in[22];
    const float* proj_b = (const float*)d_in[23];
    const float* oln_g  = (const float*)d_in[24];
    const float* oln_b  = (const float*)d_in[25];
    const int*   relidx = (const int*)d_in[26];
    const float* ctab   = (const float*)d_in[27];
    const float* sscale = (const float*)d_in[28];
    float* out = (float*)d_out;

    int T = in_sizes[27] / 2;

    float *p_t, *p_qkvs, *p_pooled, *p_ao, *p_tmp, *p_Wcat, *p_bcat, *p_kvp;
    cudaGetSymbolAddress((void**)&p_t, g_t);
    cudaGetSymbolAddress((void**)&p_qkvs, g_qkvs);
    cudaGetSymbolAddress((void**)&p_pooled, g_pooled);
    cudaGetSymbolAddress((void**)&p_kvp, g_kvp);
    cudaGetSymbolAddress((void**)&p_ao, g_ao);
    cudaGetSymbolAddress((void**)&p_tmp, g_tmp);
    cudaGetSymbolAddress((void**)&p_Wcat, g_Wcat);
    cudaGetSymbolAddress((void**)&p_bcat, g_bcat);

    int attn_smem = 25952 * 4;
    int conv_smem = 14848 * 4;
    int gemm128_smem = (4608 * 2 + 128 * 36 * 2) * 4;
    int gemm64_smem  = (4608 * 2 + 64 * 36 * 2) * 4;

    cudaFuncSetAttribute(k_attn, cudaFuncAttributeMaxDynamicSharedMemorySize, attn_smem);
    cudaFuncSetAttribute(k_conv_tc, cudaFuncAttributeMaxDynamicSharedMemorySize, conv_smem);
    cudaFuncSetAttribute(k_gemm_tc<128>, cudaFuncAttributeMaxDynamicSharedMemorySize, gemm128_smem);
    cudaFuncSetAttribute(k_gemm_tc<64>, cudaFuncAttributeMaxDynamicSharedMemorySize, gemm64_smem);

    k_prep<<<1296, 256>>>(q_w, q_b, kv_w, kv_b, sr_w, sr_b, lt, pe_w);
    k_prep_cpb<<<(T + 255) / 256, 256>>>(ctab, cpb1_w, cpb1_b, cpb2_w, cpb2_b, T);
    k_conv_tc<<<dim3(128, 3), 256, conv_smem>>>(x, pe_b);
    k_ln_rows<<<2048, 256>>>(pe_ln_g, pe_ln_b);
    k_gemm_tc<128><<<dim3(128, 6), 256, gemm128_smem>>>(p_t, p_Wcat, p_bcat, p_qkvs, 16384, 768);
    k_post<<<1536, 256>>>(qe, temp, sscale);
    k_pool<<<dim3(256, 4), 192>>>(norm_g, norm_b);
    k_gemm_tc<128><<<dim3(8, 3), 256, gemm128_smem>>>(p_pooled, kv_w, kv_b, p_kvp, 1024, 384);
    k_postkvp<<<64, 256>>>();
    k_attn<<<dim3(16, 8, 4), 256, attn_smem>>>(relidx, rpb, lb);
    k_gemm_tc<64><<<dim3(128, 3), 256, gemm64_smem>>>(p_ao, proj_w, proj_b, p_tmp, 16384, 192);
    k_lnout<<<dim3(128, 4), 256>>>(oln_g, oln_b, out);
}

// round 10
// speedup vs baseline: 1.1416x; 1.0071x over previous
#include <cuda_runtime.h>
#include <math.h>
#include <stdint.h>

#define BB 4
#define CC 192
#define NN 4096
#define NHEADS 8
#define HD 24
#define PLENC 256

// ---------------- device scratch ----------------
__device__ __align__(256) float g_xc[BB * NN * CC];
__device__ __align__(256) float g_t[BB * NN * CC];
__device__ __align__(256) float g_qkvs[BB * NN * 768];
__device__ __align__(256) float g_qs[BB * NHEADS * NN * HD];
__device__ __align__(256) float g_kvmap[BB * 16 * NN * HD];
__device__ __align__(256) float g_pooled[BB * PLENC * CC];
__device__ __align__(256) float g_kvp[BB * PLENC * 384];
__device__ __align__(256) float g_kpn[BB * NHEADS * PLENC * HD];
__device__ __align__(256) float g_vpn[BB * NHEADS * PLENC * HD];
__device__ __align__(256) float g_ao[BB * NN * CC];
__device__ __align__(256) float g_tmp[BB * NN * CC];
__device__ __align__(256) float g_bcat[768];
__device__ __align__(256) float g_cpb[32768 * NHEADS];
__device__ __align__(256) float g_Wc2h[1728 * 192];   // conv weights k-major, tf32-hi
__device__ __align__(256) float g_Wc2l[1728 * 192];   // tf32-lo
__device__ __align__(256) float g_Wfh[960 * 192];     // q|kv|sr|proj weights, tf32-hi
__device__ __align__(256) float g_Wfl[960 * 192];
__device__ __align__(256) float g_lt2[NHEADS * 216];
__device__ __align__(256) float g_w2[BB * NHEADS * NN * 12];

// ---------------- tf32 helpers ----------------
__device__ __forceinline__ unsigned f2tf(float f) {
    unsigned u;
    asm("cvt.rna.tf32.f32 %0, %1;" : "=r"(u) : "f"(f));
    return u;
}
__device__ __forceinline__ void split_tf(float f, unsigned& hi, unsigned& lo) {
    hi = f2tf(f);
    lo = f2tf(f - __uint_as_float(hi));
}
__device__ __forceinline__ void split_tf_f(float f, float& hi, float& lo) {
    unsigned h, l;
    split_tf(f, h, l);
    hi = __uint_as_float(h);
    lo = __uint_as_float(l);
}
__device__ __forceinline__ void mma8(float* d, const unsigned* a, const unsigned* b) {
    asm volatile(
        "mma.sync.aligned.m16n8k8.row.col.f32.tf32.tf32.f32 "
        "{%0,%1,%2,%3}, {%4,%5,%6,%7}, {%8,%9}, {%0,%1,%2,%3};"
        : "+f"(d[0]), "+f"(d[1]), "+f"(d[2]), "+f"(d[3])
        : "r"(a[0]), "r"(a[1]), "r"(a[2]), "r"(a[3]), "r"(b[0]), "r"(b[1]));
}

// ---------------- prep: split conv weights, fused GEMM weights, lt2, bias ----------------
__global__ void k_prep(const float* __restrict__ qw, const float* __restrict__ qb,
                       const float* __restrict__ kvw, const float* __restrict__ kvb,
                       const float* __restrict__ srw, const float* __restrict__ srb,
                       const float* __restrict__ projw,
                       const float* __restrict__ lt, const float* __restrict__ w) {
    int idx = blockIdx.x * 256 + threadIdx.x;
    if (idx < 331776) {   // conv weight -> k-major, pre-split
        int o = idx / 1728;
        int r = idx - o * 1728;
        int c = r / 9, t = r - c * 9;
        float hv, lv;
        split_tf_f(w[idx], hv, lv);
        int dst = (c * 9 + t) * 192 + o;
        g_Wc2h[dst] = hv;
        g_Wc2l[dst] = lv;
    }
    if (idx < 960 * 192) {
        int o = idx / 192, c = idx - o * 192;
        float v;
        if (o < 192)      v = qw[o * 192 + c];
        else if (o < 576) v = kvw[(o - 192) * 192 + c];
        else if (o < 768) v = srw[(o - 576) * 192 + c];
        else              v = projw[(o - 768) * 192 + c];
        float hv, lv;
        split_tf_f(v, hv, lv);
        g_Wfh[idx] = hv;
        g_Wfl[idx] = lv;
    }
    if (idx < 768) {
        float v;
        if (idx < 192)      v = qb[idx];
        else if (idx < 576) v = kvb[idx - 192];
        else                v = srb[idx - 576];
        g_bcat[idx] = v;
    }
    if (idx < 1728) {
        int h = idx / 216;
        int r = idx - h * 216;
        int l = r / 24, d = r - l * 24;
        g_lt2[idx] = lt[h * 216 + d * 9 + l];
    }
}

__global__ void __launch_bounds__(256) k_prep_cpb(const float* __restrict__ tab,
                           const float* __restrict__ c1w, const float* __restrict__ c1b,
                           const float* __restrict__ c2w, const float* __restrict__ c2b,
                           int T) {
    __shared__ float s1w[1024], s1b[512], s2[512 * 8];
    int tid = threadIdx.x;
#pragma unroll
    for (int i = 0; i < 4; i++) s1w[tid + i * 256] = c1w[tid + i * 256];
#pragma unroll
    for (int i = 0; i < 2; i++) s1b[tid + i * 256] = c1b[tid + i * 256];
#pragma unroll
    for (int i = 0; i < 16; i++) {
        int idx = tid + i * 256;
        int j = idx >> 3, h = idx & 7;
        s2[idx] = c2w[h * 512 + j];
    }
    __syncthreads();
    int t = blockIdx.x * 256 + tid;
    if (t >= T || t >= 32768) return;
    float t0 = tab[2 * t], t1 = tab[2 * t + 1];
    float acc[8];
#pragma unroll
    for (int h = 0; h < 8; h++) acc[h] = 0.f;
    for (int j = 0; j < 512; j++) {
        float hv = fmaxf(t0 * s1w[2 * j] + t1 * s1w[2 * j + 1] + s1b[j], 0.f);
#pragma unroll
        for (int h = 0; h < 8; h++) acc[h] += hv * s2[j * 8 + h];
    }
#pragma unroll
    for (int h = 0; h < 8; h++) g_cpb[t * 8 + h] = acc[h] + c2b[h];
}

// ---------------- conv 3x3 as implicit GEMM (3xTF32 mma, pre-split smem) ----------------
__global__ void __launch_bounds__(256) k_conv_tc(const float* __restrict__ x,
                                                 const float* __restrict__ bias) {
    extern __shared__ float sm[];
    float* s_xh = sm;
    float* s_xl = s_xh + 2240;
    float* s_wh = s_xl + 2240;
    float* s_wl = s_wh + 5184;

    int b = blockIdx.x >> 5;
    int y0 = (blockIdx.x & 31) * 2;
    int ocg = blockIdx.y;
    int tid = threadIdx.x;
    int wid = tid >> 5, lane = tid & 31;
    int g = lane >> 2, tcol = lane & 3;
    int wm0 = (wid >> 1) * 32, wn0 = (wid & 1) * 32;

    float acc[2][4][4];
#pragma unroll
    for (int a = 0; a < 2; a++)
#pragma unroll
        for (int bq = 0; bq < 4; bq++)
#pragma unroll
            for (int c = 0; c < 4; c++) acc[a][bq][c] = 0.f;

    const float* xb = x + (size_t)b * 192 * 4096;

    for (int c0 = 0; c0 < 192; c0 += 8) {
#pragma unroll
        for (int i = 0; i < 2; i++) {
            int f = tid + i * 256;
            int c = f >> 6;
            int rem = f & 63;
            int r = rem >> 4, seg = rem & 15;
            int gy = y0 - 1 + r;
            float4 v = make_float4(0.f, 0.f, 0.f, 0.f);
            if (gy >= 0 && gy < 64)
                v = *(const float4*)(xb + ((size_t)(c0 + c) * 64 + gy) * 64 + seg * 4);
            float4 hv, lv;
            split_tf_f(v.x, hv.x, lv.x); split_tf_f(v.y, hv.y, lv.y);
            split_tf_f(v.z, hv.z, lv.z); split_tf_f(v.w, hv.w, lv.w);
            int off = c * 280 + r * 68 + 1 + seg * 4;
            s_xh[off + 0] = hv.x; s_xh[off + 1] = hv.y; s_xh[off + 2] = hv.z; s_xh[off + 3] = hv.w;
            s_xl[off + 0] = lv.x; s_xl[off + 1] = lv.y; s_xl[off + 2] = lv.z; s_xl[off + 3] = lv.w;
        }
        if (tid < 64) {
            int c = tid >> 3;
            int rr = tid & 7;
            int r = rr >> 1, side = rr & 1;
            int off = c * 280 + r * 68 + (side ? 65 : 0);
            s_xh[off] = 0.f; s_xl[off] = 0.f;
        }
        // weight tile: pre-split in global — pure copy
#pragma unroll
        for (int i = 0; i < 5; i++) {
            int f = tid + i * 256;
            if (f < 1152) {
                int krow = f >> 4, seg = f & 15;
                size_t src = ((size_t)(c0 * 9) + krow) * 192 + ocg * 64 + seg * 4;
                int off = krow * 72 + seg * 4;
                *(float4*)(s_wh + off) = *(const float4*)(g_Wc2h + src);
                *(float4*)(s_wl + off) = *(const float4*)(g_Wc2l + src);
            }
        }
        __syncthreads();

#pragma unroll
        for (int t = 0; t < 9; t++) {
            int dh = t / 3, dw = t - dh * 3;
            unsigned bh[4][2], bl[4][2];
#pragma unroll
            for (int nt = 0; nt < 4; nt++) {
                int o = wn0 + nt * 8 + g;
                int kr0 = (tcol * 9 + t) * 72 + o;
                int kr1 = ((tcol + 4) * 9 + t) * 72 + o;
                bh[nt][0] = __float_as_uint(s_wh[kr0]);
                bl[nt][0] = __float_as_uint(s_wl[kr0]);
                bh[nt][1] = __float_as_uint(s_wh[kr1]);
                bl[nt][1] = __float_as_uint(s_wl[kr1]);
            }
#pragma unroll
            for (int mt = 0; mt < 2; mt++) {
                int mbase = wm0 + mt * 16;
                int rA = (mbase >> 6) + dh;
                int col0 = (mbase & 63) + g + dw;
                int base0 = tcol * 280 + rA * 68 + col0;
                int base1 = (tcol + 4) * 280 + rA * 68 + col0;
                unsigned ah[4], al[4];
                ah[0] = __float_as_uint(s_xh[base0]);
                ah[1] = __float_as_uint(s_xh[base0 + 8]);
                ah[2] = __float_as_uint(s_xh[base1]);
                ah[3] = __float_as_uint(s_xh[base1 + 8]);
                al[0] = __float_as_uint(s_xl[base0]);
                al[1] = __float_as_uint(s_xl[base0 + 8]);
                al[2] = __float_as_uint(s_xl[base1]);
                al[3] = __float_as_uint(s_xl[base1 + 8]);
#pragma unroll
                for (int nt = 0; nt < 4; nt++) {
                    mma8(acc[mt][nt], al, bh[nt]);
                    mma8(acc[mt][nt], ah, bl[nt]);
                    mma8(acc[mt][nt], ah, bh[nt]);
                }
            }
        }
        __syncthreads();
    }
    const float* bb = bias + ocg * 64;
    size_t rowbase = (size_t)b * 4096 + (size_t)y0 * 64;
#pragma unroll
    for (int mt = 0; mt < 2; mt++) {
#pragma unroll
        for (int nt = 0; nt < 4; nt++) {
            int r0 = wm0 + mt * 16 + g;
            int cc = wn0 + nt * 8 + 2 * tcol;
            float b0v = bb[cc], b1v = bb[cc + 1];
            float* o0 = g_xc + (rowbase + r0) * 192 + ocg * 64 + cc;
            o0[0] = acc[mt][nt][0] + b0v;
            o0[1] = acc[mt][nt][1] + b1v;
            float* o1 = g_xc + (rowbase + r0 + 8) * 192 + ocg * 64 + cc;
            o1[0] = acc[mt][nt][2] + b0v;
            o1[1] = acc[mt][nt][3] + b1v;
        }
    }
}

// ---------------- row LN ----------------
__global__ void k_ln_rows(const float* __restrict__ gam, const float* __restrict__ bet) {
    int row = blockIdx.x * 8 + (threadIdx.x >> 5);
    int lane = threadIdx.x & 31;
    const float* src = g_xc + (size_t)row * 192;
    float v[6];
    float s = 0.f, q = 0.f;
#pragma unroll
    for (int j = 0; j < 6; j++) {
        v[j] = src[lane + j * 32];
        s += v[j]; q += v[j] * v[j];
    }
#pragma unroll
    for (int off = 16; off; off >>= 1) {
        s += __shfl_xor_sync(0xffffffffu, s, off);
        q += __shfl_xor_sync(0xffffffffu, q, off);
    }
    float mean = s * (1.f / 192.f);
    float rstd = rsqrtf(q * (1.f / 192.f) - mean * mean + 1e-5f);
    float* dst = g_t + (size_t)row * 192;
#pragma unroll
    for (int j = 0; j < 6; j++) {
        int c = lane + j * 32;
        dst[c] = (v[j] - mean) * rstd * gam[c] + bet[c];
    }
}

// ---------------- generic GEMM (3xTF32; W pre-split in global) ----------------
template <int BN>
__global__ void __launch_bounds__(256) k_gemm_tc(const float* __restrict__ A,
                                                 const float* __restrict__ Wh,
                                                 const float* __restrict__ Wl,
                                                 const float* __restrict__ bias,
                                                 float* __restrict__ C,
                                                 int M, int Nout) {
    constexpr int NT = BN / 16;
    extern __shared__ float smg[];
    float* Ash = smg;
    float* Asl = Ash + 4608;
    float* Wsh = Asl + 4608;
    float* Wsl = Wsh + BN * 36;
    int m0 = blockIdx.x * 128, n0 = blockIdx.y * BN;
    int tid = threadIdx.x, wid = tid >> 5, lane = tid & 31;
    int g = lane >> 2, tcol = lane & 3;
    int wm0 = (wid >> 1) * 32, wn0 = (wid & 1) * (BN / 2);
    float acc[2][NT][4];
#pragma unroll
    for (int a = 0; a < 2; a++)
#pragma unroll
        for (int b = 0; b < NT; b++)
#pragma unroll
            for (int c = 0; c < 4; c++) acc[a][b][c] = 0.f;

    for (int kc = 0; kc < 192; kc += 32) {
#pragma unroll
        for (int i = 0; i < 4; i++) {
            int f = tid + i * 256;
            int row = f >> 3, seg = f & 7;
            float4 v = *(const float4*)(A + (size_t)(m0 + row) * 192 + kc + seg * 4);
            float4 hv, lv;
            split_tf_f(v.x, hv.x, lv.x); split_tf_f(v.y, hv.y, lv.y);
            split_tf_f(v.z, hv.z, lv.z); split_tf_f(v.w, hv.w, lv.w);
            int off = row * 36 + seg * 4;
            *(float4*)(Ash + off) = hv;
            *(float4*)(Asl + off) = lv;
        }
#pragma unroll
        for (int i = 0; i < BN / 32; i++) {
            int f = tid + i * 256;
            int row = f >> 3, seg = f & 7;
            size_t src = (size_t)(n0 + row) * 192 + kc + seg * 4;
            int off = row * 36 + seg * 4;
            *(float4*)(Wsh + off) = *(const float4*)(Wh + src);
            *(float4*)(Wsl + off) = *(const float4*)(Wl + src);
        }
        __syncthreads();
#pragma unroll
        for (int kk = 0; kk < 32; kk += 8) {
            unsigned bh[NT][2], bl[NT][2];
#pragma unroll
            for (int nt = 0; nt < NT; nt++) {
                int wr = (wn0 + nt * 8 + g) * 36;
                bh[nt][0] = __float_as_uint(Wsh[wr + kk + tcol]);
                bl[nt][0] = __float_as_uint(Wsl[wr + kk + tcol]);
                bh[nt][1] = __float_as_uint(Wsh[wr + kk + 4 + tcol]);
                bl[nt][1] = __float_as_uint(Wsl[wr + kk + 4 + tcol]);
            }
#pragma unroll
            for (int mt = 0; mt < 2; mt++) {
                int r = wm0 + mt * 16 + g;
                int ar = r * 36, ar8 = (r + 8) * 36;
                unsigned ah[4], al[4];
                ah[0] = __float_as_uint(Ash[ar + kk + tcol]);
                ah[1] = __float_as_uint(Ash[ar8 + kk + tcol]);
                ah[2] = __float_as_uint(Ash[ar + kk + 4 + tcol]);
                ah[3] = __float_as_uint(Ash[ar8 + kk + 4 + tcol]);
                al[0] = __float_as_uint(Asl[ar + kk + tcol]);
                al[1] = __float_as_uint(Asl[ar8 + kk + tcol]);
                al[2] = __float_as_uint(Asl[ar + kk + 4 + tcol]);
                al[3] = __float_as_uint(Asl[ar8 + kk + 4 + tcol]);
#pragma unroll
                for (int nt = 0; nt < NT; nt++) {
                    mma8(acc[mt][nt], al, bh[nt]);
                    mma8(acc[mt][nt], ah, bl[nt]);
                    mma8(acc[mt][nt], ah, bh[nt]);
                }
            }
        }
        __syncthreads();
    }
#pragma unroll
    for (int mt = 0; mt < 2; mt++)
#pragma unroll
        for (int nt = 0; nt < NT; nt++) {
            int r = m0 + wm0 + mt * 16 + g;
            int cc = n0 + wn0 + nt * 8 + 2 * tcol;
            float b0v = bias[cc], b1v = bias[cc + 1];
            C[(size_t)r * Nout + cc]           = acc[mt][nt][0] + b0v;
            C[(size_t)r * Nout + cc + 1]       = acc[mt][nt][1] + b1v;
            C[(size_t)(r + 8) * Nout + cc]     = acc[mt][nt][2] + b0v;
            C[(size_t)(r + 8) * Nout + cc + 1] = acc[mt][nt][3] + b1v;
        }
}

// ---------------- fused post: q l2norm/scale (+ qn.lt) + kv l2norm/relayout ----------------
__global__ void k_post(const float* __restrict__ qe, const float* __restrict__ temp,
                       const float* __restrict__ seqscale) {
    int idx = blockIdx.x * 256 + threadIdx.x;
    int g = idx % 24;
    int bn = idx / 24;
    int n = bn & 4095; int b = bn >> 12;
    if (g < 8) {
        int h = g;
        const float4* q4 = (const float4*)(g_qkvs + (size_t)bn * 768 + h * 24);
        float v[24]; float s = 0.f;
#pragma unroll
        for (int i = 0; i < 6; i++) {
            float4 t = q4[i];
            v[4 * i] = t.x; v[4 * i + 1] = t.y; v[4 * i + 2] = t.z; v[4 * i + 3] = t.w;
        }
#pragma unroll
        for (int d = 0; d < 24; d++) s += v[d] * v[d];
        float rn = 1.f / fmaxf(sqrtf(s), 1e-12f);
        float sp = log1pf(expf(temp[h]));
        float ss = seqscale[n];
        size_t ob = ((size_t)(b * 8 + h) * 4096 + n) * 24;
        float qn[24];
        float4* qs4 = (float4*)(g_qs + ob);
#pragma unroll
        for (int i = 0; i < 6; i++) {
            float4 c;
            float a0 = v[4 * i] * rn, a1 = v[4 * i + 1] * rn;
            float a2 = v[4 * i + 2] * rn, a3 = v[4 * i + 3] * rn;
            c.x = (a0 + qe[h * 24 + 4 * i])     * sp * ss;
            c.y = (a1 + qe[h * 24 + 4 * i + 1]) * sp * ss;
            c.z = (a2 + qe[h * 24 + 4 * i + 2]) * sp * ss;
            c.w = (a3 + qe[h * 24 + 4 * i + 3]) * sp * ss;
            qs4[i] = c;
            qn[4 * i] = a0; qn[4 * i + 1] = a1; qn[4 * i + 2] = a2; qn[4 * i + 3] = a3;
        }
        size_t ob2 = ((size_t)(b * 8 + h) * 4096 + n) * 12;
        const float* ltr = g_lt2 + h * 216;
#pragma unroll
        for (int l = 0; l < 9; l++) {
            float p = 0.f;
#pragma unroll
            for (int d = 0; d < 24; d++) p += qn[d] * ltr[l * 24 + d];
            g_w2[ob2 + l] = p;
        }
    } else {
        int gg = g - 8;
        const float4* src4 = (const float4*)(g_qkvs + (size_t)bn * 768 + 192 + gg * 24);
        float v[24]; float s = 0.f;
#pragma unroll
        for (int i = 0; i < 6; i++) {
            float4 t = src4[i];
            v[4 * i] = t.x; v[4 * i + 1] = t.y; v[4 * i + 2] = t.z; v[4 * i + 3] = t.w;
        }
#pragma unroll
        for (int d = 0; d < 24; d++) s += v[d] * v[d];
        float rn = 1.f;
        if (gg < 8) rn = 1.f / fmaxf(sqrtf(s), 1e-12f);
        size_t ob = ((size_t)(b * 16 + gg) * 4096 + n) * 24;
        float4* dst4 = (float4*)(g_kvmap + ob);
#pragma unroll
        for (int i = 0; i < 6; i++) {
            float4 o;
            o.x = v[4 * i] * rn; o.y = v[4 * i + 1] * rn;
            o.z = v[4 * i + 2] * rn; o.w = v[4 * i + 3] * rn;
            dst4[i] = o;
        }
    }
}

// ---------------- gelu + 4x4 pool + LN ----------------
__global__ void k_pool(const float* __restrict__ ng, const float* __restrict__ nb) {
    __shared__ float r1[192], r2[192];
    int b = blockIdx.y, m = blockIdx.x;
    int c = threadIdx.x;
    int ph = m >> 4, pw = m & 15;
    float acc = 0.f;
#pragma unroll
    for (int i = 0; i < 4; i++)
#pragma unroll
        for (int j = 0; j < 4; j++) {
            int n = (ph * 4 + i) * 64 + pw * 4 + j;
            float v = g_qkvs[((size_t)(b * 4096 + n)) * 768 + 576 + c];
            acc += 0.5f * v * (1.f + erff(v * 0.70710678118654752f));
        }
    acc *= (1.f / 16.f);
    r1[c] = acc; r2[c] = acc * acc;
    __syncthreads();
    if (c < 64) { r1[c] += r1[c + 64] + r1[c + 128]; r2[c] += r2[c + 64] + r2[c + 128]; }
    __syncthreads();
    for (int s2 = 32; s2 > 0; s2 >>= 1) {
        if (c < s2) { r1[c] += r1[c + s2]; r2[c] += r2[c + s2]; }
        __syncthreads();
    }
    float mean = r1[0] * (1.f / 192.f);
    float var = r2[0] * (1.f / 192.f) - mean * mean;
    float rstd = rsqrtf(var + 1e-5f);
    g_pooled[((size_t)(b * 256 + m)) * 192 + c] = (acc - mean) * rstd * ng[c] + nb[c];
}

// ---------------- post pooled kv ----------------
__global__ void k_postkvp() {
    int idx = blockIdx.x * 256 + threadIdx.x;
    int g = idx & 15; int bm = idx >> 4;
    int m = bm & 255; int b = bm >> 8;
    const float4* src4 = (const float4*)(g_kvp + (size_t)bm * 384 + g * 24);
    float v[24]; float s = 0.f;
#pragma unroll
    for (int i = 0; i < 6; i++) {
        float4 t = src4[i];
        v[4 * i] = t.x; v[4 * i + 1] = t.y; v[4 * i + 2] = t.z; v[4 * i + 3] = t.w;
    }
#pragma unroll
    for (int d = 0; d < 24; d++) s += v[d] * v[d];
    if (g < 8) {
        float rn = 1.f / fmaxf(sqrtf(s), 1e-12f);
        float4* dst4 = (float4*)(g_kpn + ((size_t)(b * 8 + g) * 256 + m) * 24);
#pragma unroll
        for (int i = 0; i < 6; i++) {
            float4 o;
            o.x = v[4 * i] * rn; o.y = v[4 * i + 1] * rn;
            o.z = v[4 * i + 2] * rn; o.w = v[4 * i + 3] * rn;
            dst4[i] = o;
        }
    } else {
        float4* dst4 = (float4*)(g_vpn + ((size_t)(b * 8 + g - 8) * 256 + m) * 24);
#pragma unroll
        for (int i = 0; i < 6; i++) {
            float4 o;
            o.x = v[4 * i]; o.y = v[4 * i + 1]; o.z = v[4 * i + 2]; o.w = v[4 * i + 3];
            dst4[i] = o;
        }
    }
}

// ---------------- fused attention (2 queries per warp per iteration) ----------------
// smem: sk 7776 | skp[m][28] 7168 | svp[d][260] 6240 | slog 16*296=4736 | srpb 16 | slb 16
__global__ void __launch_bounds__(256) k_attn(const int* __restrict__ rel_idx,
                                              const float* __restrict__ rpb,
                                              const float* __restrict__ lb) {
    extern __shared__ float sm[];
    float* sk  = sm;
    float* skp = sk + 7776;
    float* svp = skp + 7168;
    float* slog = svp + 6240;
    float* srpb = slog + 4736;
    float* slb = srpb + 16;

    int b = blockIdx.z, h = blockIdx.y;
    int Y0 = (blockIdx.x >> 2) * 16, X0 = (blockIdx.x & 3) * 16;
    int tid = threadIdx.x;

    const float* kbase = g_kvmap + ((size_t)(b * 16 + h) * 4096) * 24;
    const float* vbase = g_kvmap + ((size_t)(b * 16 + 8 + h) * 4096) * 24;
    for (int idx = tid; idx < 7776; idx += 256) {
        int d = idx % 24; int r = idx / 24;
        int xx = r % 18;  int yy = r / 18;
        int gy = Y0 - 1 + yy, gx = X0 - 1 + xx;
        float kv = 0.f;
        if (gy >= 0 && gy < 64 && gx >= 0 && gx < 64)
            kv = kbase[(size_t)(gy * 64 + gx) * 24 + d];
        sk[idx] = kv;
    }
    const float* kp = g_kpn + (size_t)(b * 8 + h) * 256 * 24;
    const float* vp = g_vpn + (size_t)(b * 8 + h) * 256 * 24;
    for (int f = tid; f < 1536; f += 256) {
        int m = f / 6, q = f - m * 6;
        *(float4*)(skp + m * 28 + q * 4) = *(const float4*)(kp + m * 24 + q * 4);
    }
    for (int f = tid; f < 1024; f += 256) {
        int m = f >> 2, d = 24 + (f & 3);
        skp[m * 28 + d] = 0.f;
    }
    for (int idx = tid; idx < 6240; idx += 256) {
        int d = idx / 260, m = idx - d * 260;
        svp[idx] = (m < 256) ? vp[m * 24 + d] : 0.f;
    }
    if (tid < 9) { srpb[tid] = rpb[h * 9 + tid]; slb[tid] = lb[h * 9 + tid]; }
    __syncthreads();

    int w = tid >> 5, ln = tid & 31;
    float* mylogA = slog + w * 296;
    float* mylogB = slog + (8 + w) * 296;
    const unsigned FULL = 0xffffffffu;
    size_t bh4096 = (size_t)(b * 8 + h) * 4096;

    for (int it = 0; it < 16; it++) {
        int qiA = it * 16 + w;
        int qiB = qiA + 8;
        int tyA = qiA >> 4, txA = qiA & 15;
        int tyB = qiB >> 4, txB = qiB & 15;
        int gyA = Y0 + tyA, gxA = X0 + txA;
        int gyB = Y0 + tyB, gxB = X0 + txB;
        int nA = gyA * 64 + gxA, nB = gyB * 64 + gxB;

        float qsA = 0.f, qsB = 0.f;
        if (ln < 24) {
            qsA = g_qs[(bh4096 + nA) * 24 + ln];
            qsB = g_qs[(bh4096 + nB) * 24 + ln];
        }
        float qallA[24], qallB[24];
#pragma unroll
        for (int d = 0; d < 24; d++) {
            qallA[d] = __shfl_sync(FULL, qsA, d);
            qallB[d] = __shfl_sync(FULL, qsB, d);
        }

        // lane-parallel local logits: lanes 0..8 -> A, lanes 16..24 -> B
        float w2v = 0.f;
        if (ln < 9) {
            w2v = g_w2[(bh4096 + nA) * 12 + ln];
            int dh = ln / 3 - 1, dw = ln % 3 - 1;
            bool lvalid = (gyA + dh >= 0) && (gyA + dh < 64) && (gxA + dw >= 0) && (gxA + dw < 64);
            const float* krow = sk + ((tyA + 1 + dh) * 18 + (txA + 1 + dw)) * 24;
            float4 k0 = *(const float4*)(krow);
            float4 k1 = *(const float4*)(krow + 4);
            float4 k2 = *(const float4*)(krow + 8);
            float4 k3 = *(const float4*)(krow + 12);
            float4 k4 = *(const float4*)(krow + 16);
            float4 k5 = *(const float4*)(krow + 20);
            float p1 = qallA[0]  * k0.x + qallA[1]  * k0.y + qallA[2]  * k0.z + qallA[3]  * k0.w
                     + qallA[4]  * k1.x + qallA[5]  * k1.y + qallA[6]  * k1.z + qallA[7]  * k1.w
                     + qallA[8]  * k2.x + qallA[9]  * k2.y + qallA[10] * k2.z + qallA[11] * k2.w
                     + qallA[12] * k3.x + qallA[13] * k3.y + qallA[14] * k3.z + qallA[15] * k3.w
                     + qallA[16] * k4.x + qallA[17] * k4.y + qallA[18] * k4.z + qallA[19] * k4.w
                     + qallA[20] * k5.x + qallA[21] * k5.y + qallA[22] * k5.z + qallA[23] * k5.w;
            mylogA[ln] = lvalid ? (p1 + srpb[ln]) : -1e30f;
        } else if (ln >= 16 && ln < 25) {
            int l = ln - 16;
            w2v = g_w2[(bh4096 + nB) * 12 + l];
            int dh = l / 3 - 1, dw = l % 3 - 1;
            bool lvalid = (gyB + dh >= 0) && (gyB + dh < 64) && (gxB + dw >= 0) && (gxB + dw < 64);
            const float* krow = sk + ((tyB + 1 + dh) * 18 + (txB + 1 + dw)) * 24;
            float4 k0 = *(const float4*)(krow);
            float4 k1 = *(const float4*)(krow + 4);
            float4 k2 = *(const float4*)(krow + 8);
            float4 k3 = *(const float4*)(krow + 12);
            float4 k4 = *(const float4*)(krow + 16);
            float4 k5 = *(const float4*)(krow + 20);
            float p1 = qallB[0]  * k0.x + qallB[1]  * k0.y + qallB[2]  * k0.z + qallB[3]  * k0.w
                     + qallB[4]  * k1.x + qallB[5]  * k1.y + qallB[6]  * k1.z + qallB[7]  * k1.w
                     + qallB[8]  * k2.x + qallB[9]  * k2.y + qallB[10] * k2.z + qallB[11] * k2.w
                     + qallB[12] * k3.x + qallB[13] * k3.y + qallB[14] * k3.z + qallB[15] * k3.w
                     + qallB[16] * k4.x + qallB[17] * k4.y + qallB[18] * k4.z + qallB[19] * k4.w
                     + qallB[20] * k5.x + qallB[21] * k5.y + qallB[22] * k5.z + qallB[23] * k5.w;
            mylogB[l] = lvalid ? (p1 + srpb[l]) : -1e30f;
        }

        // pool logits: shared K-row load serves both queries
        const int* riA = rel_idx + (size_t)nA * 256;
        const int* riB = rel_idx + (size_t)nB * 256;
#pragma unroll
        for (int bm = 0; bm < 8; bm++) {
            int m = bm * 32 + ln;
            float aA = g_cpb[(size_t)riA[m] * 8 + h];
            float aB = g_cpb[(size_t)riB[m] * 8 + h];
            const float* row = skp + m * 28;
            float4 k0 = *(const float4*)(row);
            float4 k1 = *(const float4*)(row + 4);
            float4 k2 = *(const float4*)(row + 8);
            float4 k3 = *(const float4*)(row + 12);
            float4 k4 = *(const float4*)(row + 16);
            float4 k5 = *(const float4*)(row + 20);
            aA += qallA[0]  * k0.x + qallA[1]  * k0.y + qallA[2]  * k0.z + qallA[3]  * k0.w;
            aB += qallB[0]  * k0.x + qallB[1]  * k0.y + qallB[2]  * k0.z + qallB[3]  * k0.w;
            aA += qallA[4]  * k1.x + qallA[5]  * k1.y + qallA[6]  * k1.z + qallA[7]  * k1.w;
            aB += qallB[4]  * k1.x + qallB[5]  * k1.y + qallB[6]  * k1.z + qallB[7]  * k1.w;
            aA += qallA[8]  * k2.x + qallA[9]  * k2.y + qallA[10] * k2.z + qallA[11] * k2.w;
            aB += qallB[8]  * k2.x + qallB[9]  * k2.y + qallB[10] * k2.z + qallB[11] * k2.w;
            aA += qallA[12] * k3.x + qallA[13] * k3.y + qallA[14] * k3.z + qallA[15] * k3.w;
            aB += qallB[12] * k3.x + qallB[13] * k3.y + qallB[14] * k3.z + qallB[15] * k3.w;
            aA += qallA[16] * k4.x + qallA[17] * k4.y + qallA[18] * k4.z + qallA[19] * k4.w;
            aB += qallB[16] * k4.x + qallB[17] * k4.y + qallB[18] * k4.z + qallB[19] * k4.w;
            aA += qallA[20] * k5.x + qallA[21] * k5.y + qallA[22] * k5.z + qallA[23] * k5.w;
            aB += qallB[20] * k5.x + qallB[21] * k5.y + qallB[22] * k5.z + qallB[23] * k5.w;
            mylogA[32 + m] = aA;
            mylogB[32 + m] = aB;
        }
        __syncwarp();

        // prefetch local V taps (independent of softmax; guarded -> 0 = zero-pad semantics)
        float vA[9], vB[9];
        if (ln < 24) {
#pragma unroll
            for (int l = 0; l < 9; l++) {
                int dh = l / 3 - 1, dw = l % 3 - 1;
                int nyA = gyA + dh, nxA = gxA + dw;
                vA[l] = (nyA >= 0 && nyA < 64 && nxA >= 0 && nxA < 64)
                        ? vbase[(size_t)(nyA * 64 + nxA) * 24 + ln] : 0.f;
                int nyB = gyB + dh, nxB = gxB + dw;
                vB[l] = (nyB >= 0 && nyB < 64 && nxB >= 0 && nxB < 64)
                        ? vbase[(size_t)(nyB * 64 + nxB) * 24 + ln] : 0.f;
            }
        }

        // softmax (both queries)
        float mxA = -1e30f, mxB = -1e30f;
#pragma unroll
        for (int j = 0; j < 8; j++) {
            mxA = fmaxf(mxA, mylogA[32 + j * 32 + ln]);
            mxB = fmaxf(mxB, mylogB[32 + j * 32 + ln]);
        }
        if (ln < 9) {
            mxA = fmaxf(mxA, mylogA[ln]);
            mxB = fmaxf(mxB, mylogB[ln]);
        }
#pragma unroll
        for (int off = 16; off > 0; off >>= 1) {
            mxA = fmaxf(mxA, __shfl_xor_sync(FULL, mxA, off));
            mxB = fmaxf(mxB, __shfl_xor_sync(FULL, mxB, off));
        }
        float sumA = 0.f, sumB = 0.f;
#pragma unroll
        for (int j = 0; j < 8; j++) {
            int i = 32 + j * 32 + ln;
            float eA = expf(mylogA[i] - mxA); mylogA[i] = eA; sumA += eA;
            float eB = expf(mylogB[i] - mxB); mylogB[i] = eB; sumB += eB;
        }
        if (ln < 9) {
            float eA = expf(mylogA[ln] - mxA); mylogA[ln] = eA; sumA += eA;
            float eB = expf(mylogB[ln] - mxB); mylogB[ln] = eB; sumB += eB;
        }
#pragma unroll
        for (int off = 16; off > 0; off >>= 1) {
            sumA += __shfl_xor_sync(FULL, sumA, off);
            sumB += __shfl_xor_sync(FULL, sumB, off);
        }
        float invA = 1.f / sumA, invB = 1.f / sumB;
        __syncwarp();
#pragma unroll
        for (int j = 0; j < 8; j++) {
            mylogA[32 + j * 32 + ln] *= invA;
            mylogB[32 + j * 32 + ln] *= invB;
        }
        if (ln < 9)                 mylogA[ln]      = w2v + slb[ln]      + mylogA[ln] * invA;
        else if (ln >= 16 && ln < 25) mylogB[ln - 16] = w2v + slb[ln - 16] + mylogB[ln - 16] * invB;
        __syncwarp();

        if (ln < 24) {
            float aA0 = 0.f, aA1 = 0.f, aB0 = 0.f, aB1 = 0.f;
#pragma unroll
            for (int l = 0; l < 9; l++) {
                aA0 += mylogA[l] * vA[l];
                aB0 += mylogB[l] * vB[l];
            }
            const float* vrow = svp + ln * 260;
#pragma unroll
            for (int m = 0; m < 256; m += 8) {
                float4 v0 = *(const float4*)(vrow + m);
                float4 v1 = *(const float4*)(vrow + m + 4);
                float4 wA0 = *(const float4*)(mylogA + 32 + m);
                float4 wA1 = *(const float4*)(mylogA + 36 + m);
                float4 wB0 = *(const float4*)(mylogB + 32 + m);
                float4 wB1 = *(const float4*)(mylogB + 36 + m);
                aA0 += wA0.x * v0.x + wA0.y * v0.y + wA0.z * v0.z + wA0.w * v0.w;
                aB0 += wB0.x * v0.x + wB0.y * v0.y + wB0.z * v0.z + wB0.w * v0.w;
                aA1 += wA1.x * v1.x + wA1.y * v1.y + wA1.z * v1.z + wA1.w * v1.w;
                aB1 += wB1.x * v1.x + wB1.y * v1.y + wB1.z * v1.z + wB1.w * v1.w;
            }
            g_ao[((size_t)(b * 4096 + nA)) * 192 + h * 24 + ln] = aA0 + aA1;
            g_ao[((size_t)(b * 4096 + nB)) * 192 + h * 24 + ln] = aB0 + aB1;
        }
        __syncwarp();
    }
}

// ---------------- final LN + transpose to (B,C,N) ----------------
__global__ void k_lnout(const float* __restrict__ gam, const float* __restrict__ bet,
                        float* __restrict__ out) {
    __shared__ float s[192 * 33];
    __shared__ float red[2][8][32];
    __shared__ float smean[32], srstd[32];
    int b = blockIdx.y, n0 = blockIdx.x * 32;
    int tx = threadIdx.x & 31, ty = threadIdx.x >> 5;
    for (int idx = threadIdx.x; idx < 32 * 192; idx += 256) {
        int i = idx / 192, c = idx - i * 192;
        s[c * 33 + i] = g_tmp[((size_t)(b * 4096 + n0 + i)) * 192 + c];
    }
    __syncthreads();
    float sum = 0.f, sq = 0.f;
    for (int c = ty; c < 192; c += 8) {
        float v = s[c * 33 + tx];
        sum += v; sq += v * v;
    }
    red[0][ty][tx] = sum; red[1][ty][tx] = sq;
    __syncthreads();
    if (ty == 0) {
        float s1 = 0.f, s2 = 0.f;
#pragma unroll
        for (int k = 0; k < 8; k++) { s1 += red[0][k][tx]; s2 += red[1][k][tx]; }
        float m = s1 * (1.f / 192.f);
        float var = s2 * (1.f / 192.f) - m * m;
        smean[tx] = m; srstd[tx] = rsqrtf(var + 1e-5f);
    }
    __syncthreads();
    for (int c = ty; c < 192; c += 8)
        out[(size_t)(b * 192 + c) * 4096 + n0 + tx] =
            (s[c * 33 + tx] - smean[tx]) * srstd[tx] * gam[c] + bet[c];
}

// ---------------- launch ----------------
extern "C" void kernel_launch(void* const* d_in, const int* in_sizes, int n_in,
                              void* d_out, int out_size) {
    const float* x      = (const float*)d_in[0];
    const float* pe_w   = (const float*)d_in[1];
    const float* pe_b   = (const float*)d_in[2];
    const float* pe_ln_g= (const float*)d_in[3];
    const float* pe_ln_b= (const float*)d_in[4];
    const float* q_w    = (const float*)d_in[5];
    const float* q_b    = (const float*)d_in[6];
    const float* kv_w   = (const float*)d_in[7];
    const float* kv_b   = (const float*)d_in[8];
    const float* sr_w   = (const float*)d_in[9];
    const float* sr_b   = (const float*)d_in[10];
    const float* norm_g = (const float*)d_in[11];
    const float* norm_b = (const float*)d_in[12];
    const float* cpb1_w = (const float*)d_in[13];
    const float* cpb1_b = (const float*)d_in[14];
    const float* cpb2_w = (const float*)d_in[15];
    const float* cpb2_b = (const float*)d_in[16];
    const float* rpb    = (const float*)d_in[17];
    const float* lt     = (const float*)d_in[18];
    const float* lb     = (const float*)d_in[19];
    const float* qe     = (const float*)d_in[20];
    const float* temp   = (const float*)d_in[21];
    const float* proj_w = (const float*)d_in[22];
    const float* proj_b = (const float*)d_in[23];
    const float* oln_g  = (const float*)d_in[24];
    const float* oln_b  = (const float*)d_in[25];
    const int*   relidx = (const int*)d_in[26];
    const float* ctab   = (const float*)d_in[27];
    const float* sscale = (const float*)d_in[28];
    float* out = (float*)d_out;

    int T = in_sizes[27] / 2;

    float *p_t, *p_qkvs, *p_pooled, *p_ao, *p_tmp, *p_bcat, *p_kvp, *p_Wfh, *p_Wfl;
    cudaGetSymbolAddress((void**)&p_t, g_t);
    cudaGetSymbolAddress((void**)&p_qkvs, g_qkvs);
    cudaGetSymbolAddress((void**)&p_pooled, g_pooled);
    cudaGetSymbolAddress((void**)&p_kvp, g_kvp);
    cudaGetSymbolAddress((void**)&p_ao, g_ao);
    cudaGetSymbolAddress((void**)&p_tmp, g_tmp);
    cudaGetSymbolAddress((void**)&p_bcat, g_bcat);
    cudaGetSymbolAddress((void**)&p_Wfh, g_Wfh);
    cudaGetSymbolAddress((void**)&p_Wfl, g_Wfl);

    int attn_smem = 25952 * 4;
    int conv_smem = 14848 * 4;
    int gemm128_smem = (4608 * 2 + 128 * 36 * 2) * 4;
    int gemm64_smem  = (4608 * 2 + 64 * 36 * 2) * 4;

    cudaFuncSetAttribute(k_attn, cudaFuncAttributeMaxDynamicSharedMemorySize, attn_smem);
    cudaFuncSetAttribute(k_conv_tc, cudaFuncAttributeMaxDynamicSharedMemorySize, conv_smem);
    cudaFuncSetAttribute(k_gemm_tc<128>, cudaFuncAttributeMaxDynamicSharedMemorySize, gemm128_smem);
    cudaFuncSetAttribute(k_gemm_tc<64>, cudaFuncAttributeMaxDynamicSharedMemorySize, gemm64_smem);

    k_prep<<<1296, 256>>>(q_w, q_b, kv_w, kv_b, sr_w, sr_b, proj_w, lt, pe_w);
    k_prep_cpb<<<(T + 255) / 256, 256>>>(ctab, cpb1_w, cpb1_b, cpb2_w, cpb2_b, T);
    k_conv_tc<<<dim3(128, 3), 256, conv_smem>>>(x, pe_b);
    k_ln_rows<<<2048, 256>>>(pe_ln_g, pe_ln_b);
    k_gemm_tc<128><<<dim3(128, 6), 256, gemm128_smem>>>(p_t, p_Wfh, p_Wfl, p_bcat, p_qkvs, 16384, 768);
    k_post<<<1536, 256>>>(qe, temp, sscale);
    k_pool<<<dim3(256, 4), 192>>>(norm_g, norm_b);
    k_gemm_tc<128><<<dim3(8, 3), 256, gemm128_smem>>>(p_pooled, p_Wfh + 192 * 192, p_Wfl + 192 * 192, kv_b, p_kvp, 1024, 384);
    k_postkvp<<<64, 256>>>();
    k_attn<<<dim3(16, 8, 4), 256, attn_smem>>>(relidx, rpb, lb);
    k_gemm_tc<64><<<dim3(128, 3), 256, gemm64_smem>>>(p_ao, p_Wfh + 768 * 192, p_Wfl + 768 * 192, proj_b, p_tmp, 16384, 192);
    k_lnout<<<dim3(128, 4), 256>>>(oln_g, oln_b, out);
}